// round 5
// baseline (speedup 1.0000x reference)
#include <cuda_runtime.h>
#include <cuda_bf16.h>
#include <math.h>

#define Bn   8
#define Hh   128
#define Wd   128
#define Cc   192
#define Gg   6
#define GC   32
#define KK2  9
#define NFUS 162     // 108 offsets + 54 mask logits
#define M_PIX (Bn*Hh*Wd)   // 131072

// Scratch (device globals — no runtime allocation allowed)
__device__ float g_xproj [(size_t)M_PIX * Cc];
__device__ float g_tmp   [(size_t)M_PIX * Cc / 2];   // dw output as bf16
__device__ float g_offmsk[(size_t)M_PIX * NFUS];
__device__ float g_wf    [Cc * NFUS];
__device__ float g_bfuse [NFUS];
__device__ unsigned g_wfrag[12 * 2 * 24 * 64];       // w_out fragment-major bf16 hi/lo

// ---------------------------------------------------------------------------
// bf16 helpers
// ---------------------------------------------------------------------------
__device__ __forceinline__ unsigned bf16pair(float a, float b) {
    __nv_bfloat162 t = __floats2bfloat162_rn(a, b);   // a -> low half (even k)
    return *reinterpret_cast<unsigned*>(&t);
}
__device__ __forceinline__ void mma_bf16(float* d, const unsigned* a, unsigned b0, unsigned b1) {
    asm volatile(
        "mma.sync.aligned.m16n8k16.row.col.f32.bf16.bf16.f32 "
        "{%0,%1,%2,%3}, {%4,%5,%6,%7}, {%8,%9}, {%0,%1,%2,%3};\n"
        : "+f"(d[0]), "+f"(d[1]), "+f"(d[2]), "+f"(d[3])
        : "r"(a[0]), "r"(a[1]), "r"(a[2]), "r"(a[3]), "r"(b0), "r"(b1));
}

// ---------------------------------------------------------------------------
// bf16x3 tensor-core GEMM (fp32 A), fragment-major smem. Used for x_proj.
// BM=128, BN=64, BK=16, 256 threads, 8 warps (4xM, 2xN), warp tile 32x32.
// ---------------------------------------------------------------------------
template<bool SPLIT>
__global__ __launch_bounds__(256) void gemm_bf16(
    const float* __restrict__ A, const float* __restrict__ W,
    const float* __restrict__ bias, float* __restrict__ C,
    int M, int N, int K)
{
    constexpr int NSP = SPLIT ? 2 : 1;
    const int BK = 16;

    __shared__ __align__(16) unsigned As[2][NSP][8][32][4];
    __shared__ __align__(16) unsigned Bs[2][NSP][2][288];

    const int bm = blockIdx.y * 128;
    const int bn = blockIdx.x * 64;
    const int tid = threadIdx.x;
    const int wid = tid >> 5;
    const int lane = tid & 31;
    const int gid = lane >> 2;
    const int tig = lane & 3;
    const int wm = (wid & 3) * 32;
    const int wn2 = wid >> 2;

    float acc[2][4][4];
#pragma unroll
    for (int mt = 0; mt < 2; mt++)
#pragma unroll
        for (int nt = 0; nt < 4; nt++)
#pragma unroll
            for (int r = 0; r < 4; r++) acc[mt][nt][r] = 0.f;

    int a_row[2], a_kq[2];
    float4 a_pref[2];
#pragma unroll
    for (int i = 0; i < 2; i++) {
        int ch = tid + i * 256;
        a_row[i] = ch >> 2;
        a_kq[i]  = (ch & 3) * 4;
    }
    int b_kk[4], b_nn[4];
    float b_pref[4];
#pragma unroll
    for (int i = 0; i < 4; i++) {
        int idx = tid + i * 256;
        b_kk[i] = idx >> 6;
        b_nn[i] = idx & 63;
    }

    auto load_gmem = [&](int k0) {
#pragma unroll
        for (int i = 0; i < 2; i++)
            a_pref[i] = *reinterpret_cast<const float4*>(
                &A[(size_t)(bm + a_row[i]) * K + k0 + a_kq[i]]);
#pragma unroll
        for (int i = 0; i < 4; i++) {
            int ncol = bn + b_nn[i];
            b_pref[i] = (ncol < N) ? W[(size_t)(k0 + b_kk[i]) * N + ncol] : 0.f;
        }
    };

    auto store_smem = [&](int buf) {
#pragma unroll
        for (int i = 0; i < 2; i++) {
            const int r = a_row[i];
            const int mb = r >> 4;
            const int rl = r & 15;
            const int gp = rl & 7;
            const int half = rl >> 3;
            const int khalf = a_kq[i] >> 3;
            float v[4] = {a_pref[i].x, a_pref[i].y, a_pref[i].z, a_pref[i].w};
#pragma unroll
            for (int jp = 0; jp < 2; jp++) {
                int k = a_kq[i] + 2 * jp;
                int tigw = (k >> 1) & 3;
                int reg = half + 2 * khalf;
                float v0 = v[2 * jp], v1 = v[2 * jp + 1];
                unsigned hi = bf16pair(v0, v1);
                As[buf][0][mb][gp * 4 + tigw][reg] = hi;
                if (SPLIT) {
                    __nv_bfloat162 h2 = *reinterpret_cast<__nv_bfloat162*>(&hi);
                    float lo0 = v0 - __bfloat162float(h2.x);
                    float lo1 = v1 - __bfloat162float(h2.y);
                    As[buf][NSP-1][mb][gp * 4 + tigw][reg] = bf16pair(lo0, lo1);
                }
            }
        }
#pragma unroll
        for (int i = 0; i < 4; i++) {
            const int kk = b_kk[i], c = b_nn[i];
            const int wn = c >> 5, cl = c & 31;
            const int nt = cl >> 3, gd = cl & 7;
            const int pr = nt >> 1, ntl = nt & 1;
            const int tigw = (kk >> 1) & 3;
            const int which = kk >> 3;
            const int pack = kk & 1;
            const int widx = tigw * 72 + pr * 32 + gd * 4 + ntl * 2 + which;
            __nv_bfloat16 hv = __float2bfloat16(b_pref[i]);
            reinterpret_cast<unsigned short*>(&Bs[buf][0][wn][widx])[pack] =
                *reinterpret_cast<unsigned short*>(&hv);
            if (SPLIT) {
                float lo = b_pref[i] - __bfloat162float(hv);
                __nv_bfloat16 lv = __float2bfloat16(lo);
                reinterpret_cast<unsigned short*>(&Bs[buf][NSP-1][wn][widx])[pack] =
                    *reinterpret_cast<unsigned short*>(&lv);
            }
        }
    };

    load_gmem(0);
    store_smem(0);
    __syncthreads();

    int buf = 0;
    const int mb0 = wm >> 4;

    for (int k0 = 0; k0 < K; k0 += BK) {
        const bool more = (k0 + BK) < K;
        if (more) load_gmem(k0 + BK);

        unsigned afr[NSP][2][4];
        uint4 bfr[NSP][2];
#pragma unroll
        for (int s = 0; s < NSP; s++) {
#pragma unroll
            for (int mt = 0; mt < 2; mt++) {
                uint4 av = *reinterpret_cast<const uint4*>(&As[buf][s][mb0 + mt][lane][0]);
                afr[s][mt][0] = av.x; afr[s][mt][1] = av.y;
                afr[s][mt][2] = av.z; afr[s][mt][3] = av.w;
            }
#pragma unroll
            for (int pr = 0; pr < 2; pr++)
                bfr[s][pr] = *reinterpret_cast<const uint4*>(
                    &Bs[buf][s][wn2][tig * 72 + pr * 32 + gid * 4]);
        }
#pragma unroll
        for (int mt = 0; mt < 2; mt++)
#pragma unroll
            for (int pr = 0; pr < 2; pr++) {
                mma_bf16(acc[mt][2*pr],   afr[0][mt], bfr[0][pr].x, bfr[0][pr].y);
                mma_bf16(acc[mt][2*pr+1], afr[0][mt], bfr[0][pr].z, bfr[0][pr].w);
                if (SPLIT) {
                    mma_bf16(acc[mt][2*pr],   afr[0][mt], bfr[NSP-1][pr].x, bfr[NSP-1][pr].y);
                    mma_bf16(acc[mt][2*pr+1], afr[0][mt], bfr[NSP-1][pr].z, bfr[NSP-1][pr].w);
                    mma_bf16(acc[mt][2*pr],   afr[NSP-1][mt], bfr[0][pr].x, bfr[0][pr].y);
                    mma_bf16(acc[mt][2*pr+1], afr[NSP-1][mt], bfr[0][pr].z, bfr[0][pr].w);
                }
            }

        if (more) store_smem(buf ^ 1);
        __syncthreads();
        buf ^= 1;
    }

#pragma unroll
    for (int mt = 0; mt < 2; mt++) {
        int row0 = bm + wm + mt * 16 + gid;
#pragma unroll
        for (int nt = 0; nt < 4; nt++) {
            int col0 = bn + wn2 * 32 + nt * 8 + 2 * tig;
            if (col0 < N) {
                C[(size_t)row0 * N + col0]       = acc[mt][nt][0] + bias[col0];
                C[(size_t)(row0 + 8) * N + col0] = acc[mt][nt][2] + bias[col0];
            }
            if (col0 + 1 < N) {
                C[(size_t)row0 * N + col0 + 1]       = acc[mt][nt][1] + bias[col0 + 1];
                C[(size_t)(row0 + 8) * N + col0 + 1] = acc[mt][nt][3] + bias[col0 + 1];
            }
        }
    }
}

// ---------------------------------------------------------------------------
// Plain bf16 GEMM with bf16 A (dw output): A-tile load = one uint4 = 8 bf16
// per thread, which are exactly 4 fragment pairs. Same B path / epilogue.
// ---------------------------------------------------------------------------
__global__ __launch_bounds__(256) void gemm_bf16A_plain(
    const __nv_bfloat16* __restrict__ A, const float* __restrict__ W,
    const float* __restrict__ bias, float* __restrict__ C,
    int M, int N, int K)
{
    const int BK = 16;
    __shared__ __align__(16) unsigned As[2][8][32][4];
    __shared__ __align__(16) unsigned Bs[2][2][288];

    const int bm = blockIdx.y * 128;
    const int bn = blockIdx.x * 64;
    const int tid = threadIdx.x;
    const int wid = tid >> 5;
    const int lane = tid & 31;
    const int gid = lane >> 2;
    const int tig = lane & 3;
    const int wm = (wid & 3) * 32;
    const int wn2 = wid >> 2;

    float acc[2][4][4];
#pragma unroll
    for (int mt = 0; mt < 2; mt++)
#pragma unroll
        for (int nt = 0; nt < 4; nt++)
#pragma unroll
            for (int r = 0; r < 4; r++) acc[mt][nt][r] = 0.f;

    const int a_row = tid >> 1;
    const int a_kh  = tid & 1;          // which 8-k half
    uint4 a_pref;
    int b_kk[4], b_nn[4];
    float b_pref[4];
#pragma unroll
    for (int i = 0; i < 4; i++) {
        int idx = tid + i * 256;
        b_kk[i] = idx >> 6;
        b_nn[i] = idx & 63;
    }

    auto load_gmem = [&](int k0) {
        a_pref = *reinterpret_cast<const uint4*>(
            &A[(size_t)(bm + a_row) * K + k0 + a_kh * 8]);
#pragma unroll
        for (int i = 0; i < 4; i++) {
            int ncol = bn + b_nn[i];
            b_pref[i] = (ncol < N) ? W[(size_t)(k0 + b_kk[i]) * N + ncol] : 0.f;
        }
    };
    auto store_smem = [&](int buf) {
        const int mb = a_row >> 4;
        const int gp = a_row & 7;
        const int half = (a_row >> 3) & 1;
        const int reg = half + 2 * a_kh;
        As[buf][mb][gp * 4 + 0][reg] = a_pref.x;
        As[buf][mb][gp * 4 + 1][reg] = a_pref.y;
        As[buf][mb][gp * 4 + 2][reg] = a_pref.z;
        As[buf][mb][gp * 4 + 3][reg] = a_pref.w;
#pragma unroll
        for (int i = 0; i < 4; i++) {
            const int kk = b_kk[i], c = b_nn[i];
            const int wn = c >> 5, cl = c & 31;
            const int nt = cl >> 3, gd = cl & 7;
            const int pr = nt >> 1, ntl = nt & 1;
            const int tigw = (kk >> 1) & 3;
            const int which = kk >> 3;
            const int pack = kk & 1;
            const int widx = tigw * 72 + pr * 32 + gd * 4 + ntl * 2 + which;
            __nv_bfloat16 hv = __float2bfloat16(b_pref[i]);
            reinterpret_cast<unsigned short*>(&Bs[buf][wn][widx])[pack] =
                *reinterpret_cast<unsigned short*>(&hv);
        }
    };

    load_gmem(0);
    store_smem(0);
    __syncthreads();

    int buf = 0;
    const int mb0 = wm >> 4;

    for (int k0 = 0; k0 < K; k0 += BK) {
        const bool more = (k0 + BK) < K;
        if (more) load_gmem(k0 + BK);

        unsigned afr[2][4];
        uint4 bfr[2];
#pragma unroll
        for (int mt = 0; mt < 2; mt++) {
            uint4 av = *reinterpret_cast<const uint4*>(&As[buf][mb0 + mt][lane][0]);
            afr[mt][0] = av.x; afr[mt][1] = av.y; afr[mt][2] = av.z; afr[mt][3] = av.w;
        }
#pragma unroll
        for (int pr = 0; pr < 2; pr++)
            bfr[pr] = *reinterpret_cast<const uint4*>(
                &Bs[buf][wn2][tig * 72 + pr * 32 + gid * 4]);
#pragma unroll
        for (int mt = 0; mt < 2; mt++)
#pragma unroll
            for (int pr = 0; pr < 2; pr++) {
                mma_bf16(acc[mt][2*pr],   afr[mt], bfr[pr].x, bfr[pr].y);
                mma_bf16(acc[mt][2*pr+1], afr[mt], bfr[pr].z, bfr[pr].w);
            }
        if (more) store_smem(buf ^ 1);
        __syncthreads();
        buf ^= 1;
    }

#pragma unroll
    for (int mt = 0; mt < 2; mt++) {
        int row0 = bm + wm + mt * 16 + gid;
#pragma unroll
        for (int nt = 0; nt < 4; nt++) {
            int col0 = bn + wn2 * 32 + nt * 8 + 2 * tig;
            if (col0 < N) {
                C[(size_t)row0 * N + col0]       = acc[mt][nt][0] + bias[col0];
                C[(size_t)(row0 + 8) * N + col0] = acc[mt][nt][2] + bias[col0];
            }
            if (col0 + 1 < N) {
                C[(size_t)row0 * N + col0 + 1]       = acc[mt][nt][1] + bias[col0 + 1];
                C[(size_t)(row0 + 8) * N + col0 + 1] = acc[mt][nt][3] + bias[col0 + 1];
            }
        }
    }
}

// ---------------------------------------------------------------------------
// Weight fusion (exact fp32): W_f = w_pw @ [w_off | w_mask], bias_f likewise.
// ---------------------------------------------------------------------------
__global__ void fuse_weights(const float* __restrict__ wpw,
                             const float* __restrict__ woff,
                             const float* __restrict__ wmask,
                             float* __restrict__ wf)
{
    int i = blockIdx.x;
    int n = threadIdx.x;
    if (n >= NFUS) return;
    const float* wrow = wpw + (size_t)i * Cc;
    float acc = 0.f;
    if (n < 108) {
        for (int o = 0; o < Cc; o++) acc = fmaf(wrow[o], woff[(size_t)o * 108 + n], acc);
    } else {
        int n2 = n - 108;
        for (int o = 0; o < Cc; o++) acc = fmaf(wrow[o], wmask[(size_t)o * 54 + n2], acc);
    }
    wf[(size_t)i * NFUS + n] = acc;
}

__global__ void fuse_bias(const float* __restrict__ bpw,
                          const float* __restrict__ woff,
                          const float* __restrict__ wmask,
                          const float* __restrict__ boff,
                          const float* __restrict__ bmask,
                          float* __restrict__ bf)
{
    int n = threadIdx.x;
    if (n >= NFUS) return;
    float acc = (n < 108) ? boff[n] : bmask[n - 108];
    if (n < 108) {
        for (int o = 0; o < Cc; o++) acc = fmaf(bpw[o], woff[(size_t)o * 108 + n], acc);
    } else {
        int n2 = n - 108;
        for (int o = 0; o < Cc; o++) acc = fmaf(bpw[o], wmask[(size_t)o * 54 + n2], acc);
    }
    bf[n] = acc;
}

// ---------------------------------------------------------------------------
// Pack w_out into fragment-major bf16 hi/lo for the fused kernel.
// Layout: wfrag[((kt*2+s)*24 + n8)*64 + lane*2 + which]
// ---------------------------------------------------------------------------
__global__ void prep_wout(const float* __restrict__ w, unsigned* __restrict__ wfrag)
{
    int i = blockIdx.x * blockDim.x + threadIdx.x;   // over [12][24][32]
    if (i >= 12 * 24 * 32) return;
    int kt = i / (24 * 32);
    int r = i % (24 * 32);
    int n8 = r / 32;
    int lane = r % 32;
    int gid = lane >> 2, tig = lane & 3;
    int n = n8 * 8 + gid;
#pragma unroll
    for (int which = 0; which < 2; which++) {
        int k0 = kt * 16 + which * 8 + tig * 2;
        float v0 = w[(size_t)k0 * Cc + n];
        float v1 = w[(size_t)(k0 + 1) * Cc + n];
        unsigned hi = bf16pair(v0, v1);
        __nv_bfloat162 h2 = *reinterpret_cast<__nv_bfloat162*>(&hi);
        unsigned lo = bf16pair(v0 - __bfloat162float(h2.x), v1 - __bfloat162float(h2.y));
        wfrag[((kt * 2 + 0) * 24 + n8) * 64 + lane * 2 + which] = hi;
        wfrag[((kt * 2 + 1) * 24 + n8) * 64 + lane * 2 + which] = lo;
    }
}

// ---------------------------------------------------------------------------
// Depthwise 3x3 + bias + SiLU, register-blocked, bf16 output.
// ---------------------------------------------------------------------------
__global__ __launch_bounds__(256) void dw_silu(
    const float4* __restrict__ x, const float4* __restrict__ wdw,
    const float4* __restrict__ bdw, __nv_bfloat16* __restrict__ out)
{
    const int C4 = Cc / 4;        // 48
    const int RW = Wd / 4;
    const size_t total = (size_t)(M_PIX / 4) * C4;
    size_t idx = (size_t)blockIdx.x * blockDim.x + threadIdx.x;
    if (idx >= total) return;

    int c4 = (int)(idx % C4);
    int run = (int)(idx / C4);
    int w0 = (run % RW) * 4;
    int h = (run / RW) % Hh;
    int b = run / (RW * Hh);

    float4 bias = bdw[c4];
    float4 acc[4] = {bias, bias, bias, bias};
    const float4 z = make_float4(0.f, 0.f, 0.f, 0.f);

#pragma unroll
    for (int ky = 0; ky < 3; ky++) {
        int hy = h + ky - 1;
        if (hy < 0 || hy >= Hh) continue;
        const float4* row = x + ((size_t)(b * Hh + hy) * Wd) * C4 + c4;
        float4 xv[6];
        xv[0] = (w0 > 0) ? row[(size_t)(w0 - 1) * C4] : z;
#pragma unroll
        for (int t = 0; t < 4; t++) xv[1 + t] = row[(size_t)(w0 + t) * C4];
        xv[5] = (w0 + 4 < Wd) ? row[(size_t)(w0 + 4) * C4] : z;

        float4 wt[3];
#pragma unroll
        for (int kx = 0; kx < 3; kx++) wt[kx] = wdw[(ky * 3 + kx) * C4 + c4];

#pragma unroll
        for (int ow = 0; ow < 4; ow++) {
#pragma unroll
            for (int kx = 0; kx < 3; kx++) {
                float4 v = xv[ow + kx];
                acc[ow].x = fmaf(v.x, wt[kx].x, acc[ow].x);
                acc[ow].y = fmaf(v.y, wt[kx].y, acc[ow].y);
                acc[ow].z = fmaf(v.z, wt[kx].z, acc[ow].z);
                acc[ow].w = fmaf(v.w, wt[kx].w, acc[ow].w);
            }
        }
    }

#pragma unroll
    for (int ow = 0; ow < 4; ow++) {
        float4 a = acc[ow];
        a.x = a.x / (1.f + expf(-a.x));
        a.y = a.y / (1.f + expf(-a.y));
        a.z = a.z / (1.f + expf(-a.z));
        a.w = a.w / (1.f + expf(-a.w));
        uint2 pk;
        pk.x = bf16pair(a.x, a.y);
        pk.y = bf16pair(a.z, a.w);
        *reinterpret_cast<uint2*>(
            &out[((size_t)(b * Hh + h) * Wd + (w0 + ow)) * Cc + c4 * 4]) = pk;
    }
}

// ---------------------------------------------------------------------------
// FUSED: softmax + deformable bilinear sampling + final GEMM (bf16x3).
// Block = 8x8 pixel tile, 256 threads. Per group: stage 13x13x32 window of
// x_proj, sample 64px x 32ch, write bf16 hi/lo straight into fragment-major
// A smem. Then 64x192 @ 192x192 GEMM with B fragments LDG'd from the
// pre-packed L2-resident w_out (register double-buffered), out += bias.
// Dynamic smem: xs 21632 + meta 6912 + As 49152 = 77696 B.
// ---------------------------------------------------------------------------
#define SM_XS    0
#define SM_META  21632
#define SM_AS    28544
#define SM_TOTAL 77696

__global__ __launch_bounds__(256) void deform_gemm(
    const float* __restrict__ xproj, const float* __restrict__ offmsk,
    const unsigned* __restrict__ wfrag, const float* __restrict__ bias,
    float* __restrict__ out)
{
    extern __shared__ char smem_raw[];
    float2* xs = reinterpret_cast<float2*>(smem_raw + SM_XS);          // [13*13][16]
    float* s_ph = reinterpret_cast<float*>(smem_raw + SM_META);        // [64][9]
    float* s_pw = s_ph + 64 * KK2;
    float* s_a  = s_pw + 64 * KK2;
    unsigned* As = reinterpret_cast<unsigned*>(smem_raw + SM_AS);      // [2][12][4][32][4]

    const int tile = blockIdx.x;
    const int tid = threadIdx.x;
    const int wid = tid >> 5;
    const int lane = tid & 31;

    const int b  = tile >> 8;
    const int ty = (tile >> 4) & 15;
    const int tx = tile & 15;
    const int h0 = ty * 8, w0 = tx * 8;

    // ================= sampling phase: 6 groups =================
    const int half = lane >> 4;
    const int ch = lane & 15;

    for (int g = 0; g < Gg; g++) {
        if (g) __syncthreads();   // previous group done reading xs/meta

        // stage window for group g
        for (int idx = tid; idx < 13 * 13 * 8; idx += 256) {
            int cell = idx >> 3;
            int c4 = idx & 7;
            int hi = cell / 13, wi = cell % 13;
            int row = min(max(h0 - 2 + hi, 0), Hh - 1);
            int col = min(max(w0 - 2 + wi, 0), Wd - 1);
            float4 v = *reinterpret_cast<const float4*>(
                &xproj[(((size_t)(b * Hh + row)) * Wd + col) * Cc + g * GC + c4 * 4]);
            xs[cell * 16 + c4 * 2]     = make_float2(v.x, v.y);
            xs[cell * 16 + c4 * 2 + 1] = make_float2(v.z, v.w);
        }
        // meta for group g
        if (tid < 64) {
            int py = tid >> 3, px = tid & 7;
            int h = h0 + py, w = w0 + px;
            const float* om = offmsk + (((size_t)(b * Hh + h)) * Wd + w) * NFUS;
            float m[KK2], mx = -1e30f;
#pragma unroll
            for (int k = 0; k < KK2; k++) { m[k] = om[108 + g * KK2 + k]; mx = fmaxf(mx, m[k]); }
            float sum = 0.f;
#pragma unroll
            for (int k = 0; k < KK2; k++) { m[k] = expf(m[k] - mx); sum += m[k]; }
            float inv = 1.f / sum;
#pragma unroll
            for (int k = 0; k < KK2; k++) {
                float ph = (float)h + (float)(k / 3 - 1) + om[g * 18 + 2 * k]     * 0.1f;
                float pw = (float)w + (float)(k % 3 - 1) + om[g * 18 + 2 * k + 1] * 0.1f;
                s_ph[tid * KK2 + k] = fminf(fmaxf(ph, 0.f), (float)(Hh - 1));
                s_pw[tid * KK2 + k] = fminf(fmaxf(pw, 0.f), (float)(Wd - 1));
                s_a[tid * KK2 + k] = m[k] * inv;
            }
        }
        __syncthreads();

        // sample + write fragment-major bf16 hi/lo into As
        const int ktile = g * 2 + (ch >> 3);
        const int tigw = ch & 3;
        const int khalf = (ch >> 2) & 1;
#pragma unroll
        for (int pass = 0; pass < 4; pass++) {
            int p = wid * 8 + pass * 2 + half;
            float2 acc = make_float2(0.f, 0.f);
#pragma unroll
            for (int k = 0; k < KK2; k++) {
                float ph = s_ph[p * KK2 + k];
                float pw = s_pw[p * KK2 + k];
                float a  = s_a [p * KK2 + k];
                int hf = (int)ph;
                int wf = (int)pw;
                float fh = ph - (float)hf;
                float fw = pw - (float)wf;
                int hl = min(max(hf - (h0 - 2), 0), 11);
                int wl = min(max(wf - (w0 - 2), 0), 11);
                int c00 = (hl * 13 + wl) * 16 + ch;
                float2 v00 = xs[c00];
                float2 v01 = xs[c00 + 16];
                float2 v10 = xs[c00 + 13 * 16];
                float2 v11 = xs[c00 + 13 * 16 + 16];
                float tx0 = fmaf(fw, v01.x - v00.x, v00.x);
                float bx0 = fmaf(fw, v11.x - v10.x, v10.x);
                float ty0 = fmaf(fw, v01.y - v00.y, v00.y);
                float by0 = fmaf(fw, v11.y - v10.y, v10.y);
                acc.x = fmaf(a, fmaf(fh, bx0 - tx0, tx0), acc.x);
                acc.y = fmaf(a, fmaf(fh, by0 - ty0, ty0), acc.y);
            }
            int mb = p >> 4;
            int gp = p & 7;
            int half_r = (p >> 3) & 1;
            int reg = half_r + 2 * khalf;
            unsigned hi = bf16pair(acc.x, acc.y);
            __nv_bfloat162 h2 = *reinterpret_cast<__nv_bfloat162*>(&hi);
            unsigned lo = bf16pair(acc.x - __bfloat162float(h2.x),
                                   acc.y - __bfloat162float(h2.y));
            As[((0 * 12 + ktile) * 4 + mb) * 128 + (gp * 4 + tigw) * 4 + reg] = hi;
            As[((1 * 12 + ktile) * 4 + mb) * 128 + (gp * 4 + tigw) * 4 + reg] = lo;
        }
    }
    __syncthreads();

    // ================= GEMM phase: [64,192] @ [192,192] bf16x3 =================
    // 8 warps along N (24 cols each = 3 n8 tiles); all 4 m16 tiles per warp.
    const uint2* wf2 = reinterpret_cast<const uint2*>(wfrag);
    float acc[4][3][4];
#pragma unroll
    for (int mt = 0; mt < 4; mt++)
#pragma unroll
        for (int nt = 0; nt < 3; nt++)
#pragma unroll
            for (int r = 0; r < 4; r++) acc[mt][nt][r] = 0.f;

    uint2 bh[2][3], bl[2][3];
    auto loadB = [&](int kt, int pb) {
#pragma unroll
        for (int nt = 0; nt < 3; nt++) {
            int n8 = wid * 3 + nt;
            bh[pb][nt] = wf2[((kt * 2 + 0) * 24 + n8) * 32 + lane];
            bl[pb][nt] = wf2[((kt * 2 + 1) * 24 + n8) * 32 + lane];
        }
    };
    loadB(0, 0);
    int pb = 0;
#pragma unroll
    for (int kt = 0; kt < 12; kt++) {
        if (kt < 11) loadB(kt + 1, pb ^ 1);
        unsigned ah[4][4], al[4][4];
#pragma unroll
        for (int mb = 0; mb < 4; mb++) {
            uint4 u = *reinterpret_cast<const uint4*>(
                &As[((0 * 12 + kt) * 4 + mb) * 128 + lane * 4]);
            ah[mb][0] = u.x; ah[mb][1] = u.y; ah[mb][2] = u.z; ah[mb][3] = u.w;
            uint4 v = *reinterpret_cast<const uint4*>(
                &As[((1 * 12 + kt) * 4 + mb) * 128 + lane * 4]);
            al[mb][0] = v.x; al[mb][1] = v.y; al[mb][2] = v.z; al[mb][3] = v.w;
        }
#pragma unroll
        for (int mt = 0; mt < 4; mt++)
#pragma unroll
            for (int nt = 0; nt < 3; nt++) {
                mma_bf16(acc[mt][nt], ah[mt], bh[pb][nt].x, bh[pb][nt].y);
                mma_bf16(acc[mt][nt], ah[mt], bl[pb][nt].x, bl[pb][nt].y);
                mma_bf16(acc[mt][nt], al[mt], bh[pb][nt].x, bh[pb][nt].y);
            }
        pb ^= 1;
    }

    // epilogue: add bias, write fp32 output
    const int gid = lane >> 2;
    const int tig = lane & 3;
#pragma unroll
    for (int mt = 0; mt < 4; mt++) {
#pragma unroll
        for (int rr = 0; rr < 2; rr++) {
            int p = mt * 16 + rr * 8 + gid;
            size_t pix = ((size_t)(b * Hh + h0 + (p >> 3)) * Wd + w0 + (p & 7));
#pragma unroll
            for (int nt = 0; nt < 3; nt++) {
                int n = (wid * 3 + nt) * 8 + tig * 2;
                float2 v;
                v.x = acc[mt][nt][rr * 2 + 0] + bias[n];
                v.y = acc[mt][nt][rr * 2 + 1] + bias[n + 1];
                *reinterpret_cast<float2*>(&out[pix * Cc + n]) = v;
            }
        }
    }
}

// ---------------------------------------------------------------------------
// Launch
// ---------------------------------------------------------------------------
extern "C" void kernel_launch(void* const* d_in, const int* in_sizes, int n_in,
                              void* d_out, int out_size)
{
    const float* x      = (const float*)d_in[0];
    const float* w_in   = (const float*)d_in[1];
    const float* b_in   = (const float*)d_in[2];
    const float* w_dw   = (const float*)d_in[3];
    const float* b_dw   = (const float*)d_in[4];
    const float* w_pw   = (const float*)d_in[5];
    const float* b_pw   = (const float*)d_in[6];
    const float* w_off  = (const float*)d_in[7];
    const float* b_off  = (const float*)d_in[8];
    const float* w_mask = (const float*)d_in[9];
    const float* b_mask = (const float*)d_in[10];
    const float* w_out  = (const float*)d_in[11];
    const float* b_out  = (const float*)d_in[12];
    float* out = (float*)d_out;

    float *xproj, *tmp, *offmsk, *wf, *bfu;
    unsigned* wfrag;
    cudaGetSymbolAddress((void**)&xproj,  g_xproj);
    cudaGetSymbolAddress((void**)&tmp,    g_tmp);
    cudaGetSymbolAddress((void**)&offmsk, g_offmsk);
    cudaGetSymbolAddress((void**)&wf,     g_wf);
    cudaGetSymbolAddress((void**)&bfu,    g_bfuse);
    cudaGetSymbolAddress((void**)&wfrag,  g_wfrag);

    cudaFuncSetAttribute(deform_gemm, cudaFuncAttributeMaxDynamicSharedMemorySize, SM_TOTAL);

    const int M = M_PIX, K = Cc;
    dim3 blk(256);
    dim3 grid_c(3, M / 128);   // N=192
    dim3 grid_f(3, M / 128);   // N=162

    // 0. weight prep (tiny)
    fuse_weights<<<Cc, 192>>>(w_pw, w_off, w_mask, wf);
    fuse_bias<<<1, 192>>>(b_pw, w_off, w_mask, b_off, b_mask, bfu);
    prep_wout<<<(12 * 24 * 32 + 255) / 256, 256>>>(w_out, wfrag);
    // 1. x_proj = x @ w_in + b_in  (bf16x3)
    gemm_bf16<true><<<grid_c, blk>>>(x, w_in, b_in, xproj, M, Cc, K);
    // 2. depthwise 3x3 + SiLU -> bf16 tmp
    {
        size_t n = (size_t)(M_PIX / 4) * (Cc / 4);
        dw_silu<<<(unsigned)((n + 255) / 256), 256>>>(
            (const float4*)x, (const float4*)w_dw, (const float4*)b_dw,
            (__nv_bfloat16*)tmp);
    }
    // 3. [offsets|mask] = dwout_bf16 @ W_f + b_f  (plain bf16)
    gemm_bf16A_plain<<<grid_f, blk>>>((const __nv_bfloat16*)tmp, wf, bfu, offmsk, M, NFUS, K);
    // 4+5. fused softmax + deformable sampling + final GEMM -> out
    deform_gemm<<<2048, 256, SM_TOTAL>>>(xproj, offmsk, wfrag, b_out, out);
}

// round 6
// speedup vs baseline: 1.0862x; 1.0862x over previous
#include <cuda_runtime.h>
#include <cuda_bf16.h>
#include <math.h>

#define Bn   8
#define Hh   128
#define Wd   128
#define Cc   192
#define Gg   6
#define GC   32
#define KK2  9
#define NFUS 162     // 108 offsets + 54 mask logits
#define M_PIX (Bn*Hh*Wd)   // 131072

// Scratch (device globals — no runtime allocation allowed)
__device__ float g_xproj [(size_t)M_PIX * Cc];
__device__ float g_tmp   [(size_t)M_PIX * Cc / 2];   // dw output as bf16
__device__ float g_offmsk[(size_t)M_PIX * NFUS];
__device__ float g_wf    [Cc * NFUS];
__device__ float g_bfuse [NFUS];
__device__ unsigned g_wfrag_in [12 * 2 * 24 * 64];   // w_in  fragment-major bf16 hi/lo
__device__ unsigned g_wfrag_out[12 * 2 * 24 * 64];   // w_out fragment-major bf16 hi/lo
__device__ unsigned g_wffrag   [12 * 21 * 64];       // fused W fragment-major bf16 (hi), N padded->168

// ---------------------------------------------------------------------------
// bf16 helpers
// ---------------------------------------------------------------------------
__device__ __forceinline__ unsigned bf16pair(float a, float b) {
    __nv_bfloat162 t = __floats2bfloat162_rn(a, b);   // a -> low half (even k)
    return *reinterpret_cast<unsigned*>(&t);
}
__device__ __forceinline__ void mma_bf16(float* d, const unsigned* a, unsigned b0, unsigned b1) {
    asm volatile(
        "mma.sync.aligned.m16n8k16.row.col.f32.bf16.bf16.f32 "
        "{%0,%1,%2,%3}, {%4,%5,%6,%7}, {%8,%9}, {%0,%1,%2,%3};\n"
        : "+f"(d[0]), "+f"(d[1]), "+f"(d[2]), "+f"(d[3])
        : "r"(a[0]), "r"(a[1]), "r"(a[2]), "r"(a[3]), "r"(b0), "r"(b1));
}

// ---------------------------------------------------------------------------
// Pack a 192x192 row-major fp32 weight into fragment-major bf16 hi/lo.
// Layout: wfrag[((kt*2+s)*24 + n8)*64 + lane*2 + which]
// ---------------------------------------------------------------------------
__global__ void prep_w192(const float* __restrict__ w, unsigned* __restrict__ wfrag)
{
    int i = blockIdx.x * blockDim.x + threadIdx.x;   // over [12][24][32]
    if (i >= 12 * 24 * 32) return;
    int kt = i / (24 * 32);
    int r = i % (24 * 32);
    int n8 = r / 32;
    int lane = r % 32;
    int gid = lane >> 2, tig = lane & 3;
    int n = n8 * 8 + gid;
#pragma unroll
    for (int which = 0; which < 2; which++) {
        int k0 = kt * 16 + which * 8 + tig * 2;
        float v0 = w[(size_t)k0 * Cc + n];
        float v1 = w[(size_t)(k0 + 1) * Cc + n];
        unsigned hi = bf16pair(v0, v1);
        __nv_bfloat162 h2 = *reinterpret_cast<__nv_bfloat162*>(&hi);
        unsigned lo = bf16pair(v0 - __bfloat162float(h2.x), v1 - __bfloat162float(h2.y));
        wfrag[((kt * 2 + 0) * 24 + n8) * 64 + lane * 2 + which] = hi;
        wfrag[((kt * 2 + 1) * 24 + n8) * 64 + lane * 2 + which] = lo;
    }
}

// Pack fused W (fp32 [192][162]) into fragment-major bf16 (hi only), N padded to 168.
// Layout: wffrag[((kt*21 + n8)*64) + lane*2 + which]
__global__ void prep_wf(const float* __restrict__ wf, unsigned* __restrict__ wffrag)
{
    int i = blockIdx.x * blockDim.x + threadIdx.x;   // over [12][21][32]
    if (i >= 12 * 21 * 32) return;
    int kt = i / (21 * 32);
    int r = i % (21 * 32);
    int n8 = r / 32;
    int lane = r % 32;
    int gid = lane >> 2, tig = lane & 3;
    int n = n8 * 8 + gid;
#pragma unroll
    for (int which = 0; which < 2; which++) {
        int k0 = kt * 16 + which * 8 + tig * 2;
        float v0 = (n < NFUS) ? wf[(size_t)k0 * NFUS + n] : 0.f;
        float v1 = (n < NFUS) ? wf[(size_t)(k0 + 1) * NFUS + n] : 0.f;
        wffrag[(kt * 21 + n8) * 64 + lane * 2 + which] = bf16pair(v0, v1);
    }
}

// ---------------------------------------------------------------------------
// Smem-free bf16x3 GEMM: C[M,192] = A(fp32)[M,192] @ Wfrag + bias.
// Grid (3, M/256), block 256 (8 warps). Warp tile 32x64 (2 m16 x 8 n8).
// A fragments LDG'd as float2 pairs, converted hi/lo in registers.
// B fragments LDG'd from fragment-major gmem (L1 broadcast across warps).
// ---------------------------------------------------------------------------
__global__ __launch_bounds__(256) void gemm_x3_direct(
    const float* __restrict__ A, const unsigned* __restrict__ wfrag,
    const float* __restrict__ bias, float* __restrict__ C)
{
    const int tid = threadIdx.x;
    const int wid = tid >> 5;
    const int lane = tid & 31;
    const int gid = lane >> 2;
    const int tig = lane & 3;
    const int bn8 = blockIdx.x * 8;
    const int bm = blockIdx.y * 256 + wid * 32;
    const uint2* wf2 = reinterpret_cast<const uint2*>(wfrag);

    float acc[2][8][4];
#pragma unroll
    for (int mt = 0; mt < 2; mt++)
#pragma unroll
        for (int nt = 0; nt < 8; nt++)
#pragma unroll
            for (int r = 0; r < 4; r++) acc[mt][nt][r] = 0.f;

    const float* ap0[2];
    const float* ap1[2];
#pragma unroll
    for (int mt = 0; mt < 2; mt++) {
        ap0[mt] = A + (size_t)(bm + mt * 16 + gid) * Cc + tig * 2;
        ap1[mt] = A + (size_t)(bm + mt * 16 + gid + 8) * Cc + tig * 2;
    }

    float2 av[2][4];
    auto loadA = [&](int kt) {
#pragma unroll
        for (int mt = 0; mt < 2; mt++) {
            av[mt][0] = *reinterpret_cast<const float2*>(ap0[mt] + kt * 16);
            av[mt][1] = *reinterpret_cast<const float2*>(ap1[mt] + kt * 16);
            av[mt][2] = *reinterpret_cast<const float2*>(ap0[mt] + kt * 16 + 8);
            av[mt][3] = *reinterpret_cast<const float2*>(ap1[mt] + kt * 16 + 8);
        }
    };

    loadA(0);
#pragma unroll
    for (int kt = 0; kt < 12; kt++) {
        unsigned ah[2][4], al[2][4];
#pragma unroll
        for (int mt = 0; mt < 2; mt++)
#pragma unroll
            for (int r = 0; r < 4; r++) {
                float v0 = av[mt][r].x, v1 = av[mt][r].y;
                unsigned hi = bf16pair(v0, v1);
                __nv_bfloat162 h2 = *reinterpret_cast<__nv_bfloat162*>(&hi);
                ah[mt][r] = hi;
                al[mt][r] = bf16pair(v0 - __bfloat162float(h2.x),
                                     v1 - __bfloat162float(h2.y));
            }
        if (kt < 11) loadA(kt + 1);

#pragma unroll
        for (int nt = 0; nt < 8; nt++) {
            uint2 bh = wf2[(size_t)((kt * 2 + 0) * 24 + bn8 + nt) * 32 + lane];
            uint2 bl = wf2[(size_t)((kt * 2 + 1) * 24 + bn8 + nt) * 32 + lane];
#pragma unroll
            for (int mt = 0; mt < 2; mt++) {
                mma_bf16(acc[mt][nt], ah[mt], bh.x, bh.y);
                mma_bf16(acc[mt][nt], ah[mt], bl.x, bl.y);
                mma_bf16(acc[mt][nt], al[mt], bh.x, bh.y);
            }
        }
    }

#pragma unroll
    for (int mt = 0; mt < 2; mt++) {
        int row0 = bm + mt * 16 + gid;
#pragma unroll
        for (int nt = 0; nt < 8; nt++) {
            int col = (bn8 + nt) * 8 + tig * 2;
            float2 bv = *reinterpret_cast<const float2*>(&bias[col]);
            float2 v0, v1;
            v0.x = acc[mt][nt][0] + bv.x; v0.y = acc[mt][nt][1] + bv.y;
            v1.x = acc[mt][nt][2] + bv.x; v1.y = acc[mt][nt][3] + bv.y;
            *reinterpret_cast<float2*>(&C[(size_t)row0 * Cc + col]) = v0;
            *reinterpret_cast<float2*>(&C[(size_t)(row0 + 8) * Cc + col]) = v1;
        }
    }
}

// ---------------------------------------------------------------------------
// Smem-free plain bf16 GEMM: C[M,162] = A(bf16)[M,192] @ WFfrag + bias.
// Grid (3, M/256), warp tile 32x56 (2 m16 x 7 n8). A regs ARE bf16 pairs.
// ---------------------------------------------------------------------------
__global__ __launch_bounds__(256) void gemm_plain_direct(
    const __nv_bfloat16* __restrict__ A, const unsigned* __restrict__ wffrag,
    const float* __restrict__ bias, float* __restrict__ C)
{
    const int tid = threadIdx.x;
    const int wid = tid >> 5;
    const int lane = tid & 31;
    const int gid = lane >> 2;
    const int tig = lane & 3;
    const int bn8 = blockIdx.x * 7;
    const int bm = blockIdx.y * 256 + wid * 32;
    const uint2* wf2 = reinterpret_cast<const uint2*>(wffrag);

    float acc[2][7][4];
#pragma unroll
    for (int mt = 0; mt < 2; mt++)
#pragma unroll
        for (int nt = 0; nt < 7; nt++)
#pragma unroll
            for (int r = 0; r < 4; r++) acc[mt][nt][r] = 0.f;

    const __nv_bfloat16* ap0[2];
    const __nv_bfloat16* ap1[2];
#pragma unroll
    for (int mt = 0; mt < 2; mt++) {
        ap0[mt] = A + (size_t)(bm + mt * 16 + gid) * Cc + tig * 2;
        ap1[mt] = A + (size_t)(bm + mt * 16 + gid + 8) * Cc + tig * 2;
    }

    unsigned ar[2][4];
    auto loadA = [&](int kt) {
#pragma unroll
        for (int mt = 0; mt < 2; mt++) {
            ar[mt][0] = *reinterpret_cast<const unsigned*>(ap0[mt] + kt * 16);
            ar[mt][1] = *reinterpret_cast<const unsigned*>(ap1[mt] + kt * 16);
            ar[mt][2] = *reinterpret_cast<const unsigned*>(ap0[mt] + kt * 16 + 8);
            ar[mt][3] = *reinterpret_cast<const unsigned*>(ap1[mt] + kt * 16 + 8);
        }
    };

    loadA(0);
#pragma unroll
    for (int kt = 0; kt < 12; kt++) {
        unsigned a0[2][4];
#pragma unroll
        for (int mt = 0; mt < 2; mt++)
#pragma unroll
            for (int r = 0; r < 4; r++) a0[mt][r] = ar[mt][r];
        if (kt < 11) loadA(kt + 1);

#pragma unroll
        for (int nt = 0; nt < 7; nt++) {
            uint2 bh = wf2[(size_t)(kt * 21 + bn8 + nt) * 32 + lane];
#pragma unroll
            for (int mt = 0; mt < 2; mt++)
                mma_bf16(acc[mt][nt], a0[mt], bh.x, bh.y);
        }
    }

#pragma unroll
    for (int mt = 0; mt < 2; mt++) {
        int row0 = bm + mt * 16 + gid;
#pragma unroll
        for (int nt = 0; nt < 7; nt++) {
            int col = (bn8 + nt) * 8 + tig * 2;
            if (col < NFUS) {
                float b0 = bias[col];
                C[(size_t)row0 * NFUS + col]       = acc[mt][nt][0] + b0;
                C[(size_t)(row0 + 8) * NFUS + col] = acc[mt][nt][2] + b0;
            }
            if (col + 1 < NFUS) {
                float b1 = bias[col + 1];
                C[(size_t)row0 * NFUS + col + 1]       = acc[mt][nt][1] + b1;
                C[(size_t)(row0 + 8) * NFUS + col + 1] = acc[mt][nt][3] + b1;
            }
        }
    }
}

// ---------------------------------------------------------------------------
// Weight fusion (exact fp32): W_f = w_pw @ [w_off | w_mask], bias_f likewise.
// ---------------------------------------------------------------------------
__global__ void fuse_weights(const float* __restrict__ wpw,
                             const float* __restrict__ woff,
                             const float* __restrict__ wmask,
                             float* __restrict__ wf)
{
    int i = blockIdx.x;
    int n = threadIdx.x;
    if (n >= NFUS) return;
    const float* wrow = wpw + (size_t)i * Cc;
    float acc = 0.f;
    if (n < 108) {
        for (int o = 0; o < Cc; o++) acc = fmaf(wrow[o], woff[(size_t)o * 108 + n], acc);
    } else {
        int n2 = n - 108;
        for (int o = 0; o < Cc; o++) acc = fmaf(wrow[o], wmask[(size_t)o * 54 + n2], acc);
    }
    wf[(size_t)i * NFUS + n] = acc;
}

__global__ void fuse_bias(const float* __restrict__ bpw,
                          const float* __restrict__ woff,
                          const float* __restrict__ wmask,
                          const float* __restrict__ boff,
                          const float* __restrict__ bmask,
                          float* __restrict__ bf)
{
    int n = threadIdx.x;
    if (n >= NFUS) return;
    float acc = (n < 108) ? boff[n] : bmask[n - 108];
    if (n < 108) {
        for (int o = 0; o < Cc; o++) acc = fmaf(bpw[o], woff[(size_t)o * 108 + n], acc);
    } else {
        int n2 = n - 108;
        for (int o = 0; o < Cc; o++) acc = fmaf(bpw[o], wmask[(size_t)o * 54 + n2], acc);
    }
    bf[n] = acc;
}

// ---------------------------------------------------------------------------
// Depthwise 3x3 + bias + SiLU, register-blocked, bf16 output.
// ---------------------------------------------------------------------------
__global__ __launch_bounds__(256) void dw_silu(
    const float4* __restrict__ x, const float4* __restrict__ wdw,
    const float4* __restrict__ bdw, __nv_bfloat16* __restrict__ out)
{
    const int C4 = Cc / 4;        // 48
    const int RW = Wd / 4;
    const size_t total = (size_t)(M_PIX / 4) * C4;
    size_t idx = (size_t)blockIdx.x * blockDim.x + threadIdx.x;
    if (idx >= total) return;

    int c4 = (int)(idx % C4);
    int run = (int)(idx / C4);
    int w0 = (run % RW) * 4;
    int h = (run / RW) % Hh;
    int b = run / (RW * Hh);

    float4 bias = bdw[c4];
    float4 acc[4] = {bias, bias, bias, bias};
    const float4 z = make_float4(0.f, 0.f, 0.f, 0.f);

#pragma unroll
    for (int ky = 0; ky < 3; ky++) {
        int hy = h + ky - 1;
        if (hy < 0 || hy >= Hh) continue;
        const float4* row = x + ((size_t)(b * Hh + hy) * Wd) * C4 + c4;
        float4 xv[6];
        xv[0] = (w0 > 0) ? row[(size_t)(w0 - 1) * C4] : z;
#pragma unroll
        for (int t = 0; t < 4; t++) xv[1 + t] = row[(size_t)(w0 + t) * C4];
        xv[5] = (w0 + 4 < Wd) ? row[(size_t)(w0 + 4) * C4] : z;

        float4 wt[3];
#pragma unroll
        for (int kx = 0; kx < 3; kx++) wt[kx] = wdw[(ky * 3 + kx) * C4 + c4];

#pragma unroll
        for (int ow = 0; ow < 4; ow++) {
#pragma unroll
            for (int kx = 0; kx < 3; kx++) {
                float4 v = xv[ow + kx];
                acc[ow].x = fmaf(v.x, wt[kx].x, acc[ow].x);
                acc[ow].y = fmaf(v.y, wt[kx].y, acc[ow].y);
                acc[ow].z = fmaf(v.z, wt[kx].z, acc[ow].z);
                acc[ow].w = fmaf(v.w, wt[kx].w, acc[ow].w);
            }
        }
    }

#pragma unroll
    for (int ow = 0; ow < 4; ow++) {
        float4 a = acc[ow];
        a.x = a.x / (1.f + expf(-a.x));
        a.y = a.y / (1.f + expf(-a.y));
        a.z = a.z / (1.f + expf(-a.z));
        a.w = a.w / (1.f + expf(-a.w));
        uint2 pk;
        pk.x = bf16pair(a.x, a.y);
        pk.y = bf16pair(a.z, a.w);
        *reinterpret_cast<uint2*>(
            &out[((size_t)(b * Hh + h) * Wd + (w0 + ow)) * Cc + c4 * 4]) = pk;
    }
}

// ---------------------------------------------------------------------------
// FUSED: softmax + deformable bilinear sampling + final GEMM (bf16x3).
// ---------------------------------------------------------------------------
#define SM_XS    0
#define SM_META  21632
#define SM_AS    28544
#define SM_TOTAL 77696

__global__ __launch_bounds__(256) void deform_gemm(
    const float* __restrict__ xproj, const float* __restrict__ offmsk,
    const unsigned* __restrict__ wfrag, const float* __restrict__ bias,
    float* __restrict__ out)
{
    extern __shared__ char smem_raw[];
    float2* xs = reinterpret_cast<float2*>(smem_raw + SM_XS);          // [13*13][16]
    float* s_ph = reinterpret_cast<float*>(smem_raw + SM_META);        // [64][9]
    float* s_pw = s_ph + 64 * KK2;
    float* s_a  = s_pw + 64 * KK2;
    unsigned* As = reinterpret_cast<unsigned*>(smem_raw + SM_AS);      // [2][12][4][32][4]

    const int tile = blockIdx.x;
    const int tid = threadIdx.x;
    const int wid = tid >> 5;
    const int lane = tid & 31;

    const int b  = tile >> 8;
    const int ty = (tile >> 4) & 15;
    const int tx = tile & 15;
    const int h0 = ty * 8, w0 = tx * 8;

    const int half = lane >> 4;
    const int ch = lane & 15;

    for (int g = 0; g < Gg; g++) {
        if (g) __syncthreads();

        for (int idx = tid; idx < 13 * 13 * 8; idx += 256) {
            int cell = idx >> 3;
            int c4 = idx & 7;
            int hi = cell / 13, wi = cell % 13;
            int row = min(max(h0 - 2 + hi, 0), Hh - 1);
            int col = min(max(w0 - 2 + wi, 0), Wd - 1);
            float4 v = *reinterpret_cast<const float4*>(
                &xproj[(((size_t)(b * Hh + row)) * Wd + col) * Cc + g * GC + c4 * 4]);
            xs[cell * 16 + c4 * 2]     = make_float2(v.x, v.y);
            xs[cell * 16 + c4 * 2 + 1] = make_float2(v.z, v.w);
        }
        if (tid < 64) {
            int py = tid >> 3, px = tid & 7;
            int h = h0 + py, w = w0 + px;
            const float* om = offmsk + (((size_t)(b * Hh + h)) * Wd + w) * NFUS;
            float m[KK2], mx = -1e30f;
#pragma unroll
            for (int k = 0; k < KK2; k++) { m[k] = om[108 + g * KK2 + k]; mx = fmaxf(mx, m[k]); }
            float sum = 0.f;
#pragma unroll
            for (int k = 0; k < KK2; k++) { m[k] = expf(m[k] - mx); sum += m[k]; }
            float inv = 1.f / sum;
#pragma unroll
            for (int k = 0; k < KK2; k++) {
                float ph = (float)h + (float)(k / 3 - 1) + om[g * 18 + 2 * k]     * 0.1f;
                float pw = (float)w + (float)(k % 3 - 1) + om[g * 18 + 2 * k + 1] * 0.1f;
                s_ph[tid * KK2 + k] = fminf(fmaxf(ph, 0.f), (float)(Hh - 1));
                s_pw[tid * KK2 + k] = fminf(fmaxf(pw, 0.f), (float)(Wd - 1));
                s_a[tid * KK2 + k] = m[k] * inv;
            }
        }
        __syncthreads();

        const int ktile = g * 2 + (ch >> 3);
        const int tigw = ch & 3;
        const int khalf = (ch >> 2) & 1;
#pragma unroll
        for (int pass = 0; pass < 4; pass++) {
            int p = wid * 8 + pass * 2 + half;
            float2 acc = make_float2(0.f, 0.f);
#pragma unroll
            for (int k = 0; k < KK2; k++) {
                float ph = s_ph[p * KK2 + k];
                float pw = s_pw[p * KK2 + k];
                float a  = s_a [p * KK2 + k];
                int hf = (int)ph;
                int wf = (int)pw;
                float fh = ph - (float)hf;
                float fw = pw - (float)wf;
                int hl = min(max(hf - (h0 - 2), 0), 11);
                int wl = min(max(wf - (w0 - 2), 0), 11);
                int c00 = (hl * 13 + wl) * 16 + ch;
                float2 v00 = xs[c00];
                float2 v01 = xs[c00 + 16];
                float2 v10 = xs[c00 + 13 * 16];
                float2 v11 = xs[c00 + 13 * 16 + 16];
                float tx0 = fmaf(fw, v01.x - v00.x, v00.x);
                float bx0 = fmaf(fw, v11.x - v10.x, v10.x);
                float ty0 = fmaf(fw, v01.y - v00.y, v00.y);
                float by0 = fmaf(fw, v11.y - v10.y, v10.y);
                acc.x = fmaf(a, fmaf(fh, bx0 - tx0, tx0), acc.x);
                acc.y = fmaf(a, fmaf(fh, by0 - ty0, ty0), acc.y);
            }
            int mb = p >> 4;
            int gp = p & 7;
            int half_r = (p >> 3) & 1;
            int reg = half_r + 2 * khalf;
            unsigned hi = bf16pair(acc.x, acc.y);
            __nv_bfloat162 h2 = *reinterpret_cast<__nv_bfloat162*>(&hi);
            unsigned lo = bf16pair(acc.x - __bfloat162float(h2.x),
                                   acc.y - __bfloat162float(h2.y));
            As[((0 * 12 + ktile) * 4 + mb) * 128 + (gp * 4 + tigw) * 4 + reg] = hi;
            As[((1 * 12 + ktile) * 4 + mb) * 128 + (gp * 4 + tigw) * 4 + reg] = lo;
        }
    }
    __syncthreads();

    const uint2* wf2 = reinterpret_cast<const uint2*>(wfrag);
    float acc[4][3][4];
#pragma unroll
    for (int mt = 0; mt < 4; mt++)
#pragma unroll
        for (int nt = 0; nt < 3; nt++)
#pragma unroll
            for (int r = 0; r < 4; r++) acc[mt][nt][r] = 0.f;

    uint2 bh[2][3], bl[2][3];
    auto loadB = [&](int kt, int pb) {
#pragma unroll
        for (int nt = 0; nt < 3; nt++) {
            int n8 = wid * 3 + nt;
            bh[pb][nt] = wf2[((kt * 2 + 0) * 24 + n8) * 32 + lane];
            bl[pb][nt] = wf2[((kt * 2 + 1) * 24 + n8) * 32 + lane];
        }
    };
    loadB(0, 0);
    int pb = 0;
#pragma unroll
    for (int kt = 0; kt < 12; kt++) {
        if (kt < 11) loadB(kt + 1, pb ^ 1);
        unsigned ah[4][4], al[4][4];
#pragma unroll
        for (int mb = 0; mb < 4; mb++) {
            uint4 u = *reinterpret_cast<const uint4*>(
                &As[((0 * 12 + kt) * 4 + mb) * 128 + lane * 4]);
            ah[mb][0] = u.x; ah[mb][1] = u.y; ah[mb][2] = u.z; ah[mb][3] = u.w;
            uint4 v = *reinterpret_cast<const uint4*>(
                &As[((1 * 12 + kt) * 4 + mb) * 128 + lane * 4]);
            al[mb][0] = v.x; al[mb][1] = v.y; al[mb][2] = v.z; al[mb][3] = v.w;
        }
#pragma unroll
        for (int mt = 0; mt < 4; mt++)
#pragma unroll
            for (int nt = 0; nt < 3; nt++) {
                mma_bf16(acc[mt][nt], ah[mt], bh[pb][nt].x, bh[pb][nt].y);
                mma_bf16(acc[mt][nt], ah[mt], bl[pb][nt].x, bl[pb][nt].y);
                mma_bf16(acc[mt][nt], al[mt], bh[pb][nt].x, bh[pb][nt].y);
            }
        pb ^= 1;
    }

    const int gid = lane >> 2;
    const int tig = lane & 3;
#pragma unroll
    for (int mt = 0; mt < 4; mt++) {
#pragma unroll
        for (int rr = 0; rr < 2; rr++) {
            int p = mt * 16 + rr * 8 + gid;
            size_t pix = ((size_t)(b * Hh + h0 + (p >> 3)) * Wd + w0 + (p & 7));
#pragma unroll
            for (int nt = 0; nt < 3; nt++) {
                int n = (wid * 3 + nt) * 8 + tig * 2;
                float2 v;
                v.x = acc[mt][nt][rr * 2 + 0] + bias[n];
                v.y = acc[mt][nt][rr * 2 + 1] + bias[n + 1];
                *reinterpret_cast<float2*>(&out[pix * Cc + n]) = v;
            }
        }
    }
}

// ---------------------------------------------------------------------------
// Launch
// ---------------------------------------------------------------------------
extern "C" void kernel_launch(void* const* d_in, const int* in_sizes, int n_in,
                              void* d_out, int out_size)
{
    const float* x      = (const float*)d_in[0];
    const float* w_in   = (const float*)d_in[1];
    const float* b_in   = (const float*)d_in[2];
    const float* w_dw   = (const float*)d_in[3];
    const float* b_dw   = (const float*)d_in[4];
    const float* w_pw   = (const float*)d_in[5];
    const float* b_pw   = (const float*)d_in[6];
    const float* w_off  = (const float*)d_in[7];
    const float* b_off  = (const float*)d_in[8];
    const float* w_mask = (const float*)d_in[9];
    const float* b_mask = (const float*)d_in[10];
    const float* w_out  = (const float*)d_in[11];
    const float* b_out  = (const float*)d_in[12];
    float* out = (float*)d_out;

    float *xproj, *tmp, *offmsk, *wf, *bfu;
    unsigned *wfin, *wfout, *wff;
    cudaGetSymbolAddress((void**)&xproj,  g_xproj);
    cudaGetSymbolAddress((void**)&tmp,    g_tmp);
    cudaGetSymbolAddress((void**)&offmsk, g_offmsk);
    cudaGetSymbolAddress((void**)&wf,     g_wf);
    cudaGetSymbolAddress((void**)&bfu,    g_bfuse);
    cudaGetSymbolAddress((void**)&wfin,   g_wfrag_in);
    cudaGetSymbolAddress((void**)&wfout,  g_wfrag_out);
    cudaGetSymbolAddress((void**)&wff,    g_wffrag);

    cudaFuncSetAttribute(deform_gemm, cudaFuncAttributeMaxDynamicSharedMemorySize, SM_TOTAL);

    // 0. weight prep (tiny)
    fuse_weights<<<Cc, 192>>>(w_pw, w_off, w_mask, wf);
    fuse_bias<<<1, 192>>>(b_pw, w_off, w_mask, b_off, b_mask, bfu);
    prep_w192<<<(12 * 24 * 32 + 255) / 256, 256>>>(w_in, wfin);
    prep_w192<<<(12 * 24 * 32 + 255) / 256, 256>>>(w_out, wfout);
    prep_wf<<<(12 * 21 * 32 + 255) / 256, 256>>>(wf, wff);
    // 1. x_proj = x @ w_in + b_in  (bf16x3, smem-free)
    gemm_x3_direct<<<dim3(3, M_PIX / 256), 256>>>(x, wfin, b_in, xproj);
    // 2. depthwise 3x3 + SiLU -> bf16 tmp
    {
        size_t n = (size_t)(M_PIX / 4) * (Cc / 4);
        dw_silu<<<(unsigned)((n + 255) / 256), 256>>>(
            (const float4*)x, (const float4*)w_dw, (const float4*)b_dw,
            (__nv_bfloat16*)tmp);
    }
    // 3. [offsets|mask] = dwout_bf16 @ W_f + b_f  (plain bf16, smem-free)
    gemm_plain_direct<<<dim3(3, M_PIX / 256), 256>>>(
        (const __nv_bfloat16*)tmp, wff, bfu, offmsk);
    // 4+5. fused softmax + deformable sampling + final GEMM -> out
    deform_gemm<<<2048, 256, SM_TOTAL>>>(xproj, offmsk, wfout, b_out, out);
}

// round 7
// speedup vs baseline: 1.2587x; 1.1588x over previous
#include <cuda_runtime.h>
#include <cuda_bf16.h>
#include <math.h>

#define Bn   8
#define Hh   128
#define Wd   128
#define Cc   192
#define Gg   6
#define GC   32
#define KK2  9
#define NFUS 162     // 108 offsets + 54 mask logits
#define M_PIX (Bn*Hh*Wd)   // 131072

// Scratch (device globals — no runtime allocation allowed)
__device__ float g_xproj [(size_t)M_PIX * Cc];
__device__ float g_tmp   [(size_t)M_PIX * Cc / 2];   // dw output as bf16
__device__ float g_offmsk[(size_t)M_PIX * NFUS];
__device__ float g_wf    [Cc * NFUS];
__device__ float g_bfuse [NFUS];
__device__ unsigned g_wfrag_in [12 * 2 * 24 * 64];   // w_in  fragment-major bf16 hi/lo
__device__ unsigned g_wfrag_out[12 * 2 * 24 * 64];   // w_out fragment-major bf16 hi/lo
__device__ unsigned g_wffrag   [12 * 21 * 64];       // fused W fragment-major bf16 (hi), N padded->168

// ---------------------------------------------------------------------------
// bf16 helpers
// ---------------------------------------------------------------------------
__device__ __forceinline__ unsigned bf16pair(float a, float b) {
    __nv_bfloat162 t = __floats2bfloat162_rn(a, b);   // a -> low half (even k)
    return *reinterpret_cast<unsigned*>(&t);
}
__device__ __forceinline__ void mma_bf16(float* d, const unsigned* a, unsigned b0, unsigned b1) {
    asm volatile(
        "mma.sync.aligned.m16n8k16.row.col.f32.bf16.bf16.f32 "
        "{%0,%1,%2,%3}, {%4,%5,%6,%7}, {%8,%9}, {%0,%1,%2,%3};\n"
        : "+f"(d[0]), "+f"(d[1]), "+f"(d[2]), "+f"(d[3])
        : "r"(a[0]), "r"(a[1]), "r"(a[2]), "r"(a[3]), "r"(b0), "r"(b1));
}

// ---------------------------------------------------------------------------
// Weight packing (one kernel for all three packs)
// 192x192 pack layout: wfrag[((kt*2+s)*24 + n8)*64 + lane*2 + which]
// wf pack layout (hi only, N padded to 168): wffrag[(kt*21 + n8)*64 + lane*2 + which]
// ---------------------------------------------------------------------------
__device__ __forceinline__ void pack192(const float* __restrict__ w,
                                        unsigned* __restrict__ wfrag, int i)
{
    int kt = i / (24 * 32);
    int r = i % (24 * 32);
    int n8 = r / 32;
    int lane = r % 32;
    int gid = lane >> 2, tig = lane & 3;
    int n = n8 * 8 + gid;
#pragma unroll
    for (int which = 0; which < 2; which++) {
        int k0 = kt * 16 + which * 8 + tig * 2;
        float v0 = w[(size_t)k0 * Cc + n];
        float v1 = w[(size_t)(k0 + 1) * Cc + n];
        unsigned hi = bf16pair(v0, v1);
        __nv_bfloat162 h2 = *reinterpret_cast<__nv_bfloat162*>(&hi);
        unsigned lo = bf16pair(v0 - __bfloat162float(h2.x), v1 - __bfloat162float(h2.y));
        wfrag[((kt * 2 + 0) * 24 + n8) * 64 + lane * 2 + which] = hi;
        wfrag[((kt * 2 + 1) * 24 + n8) * 64 + lane * 2 + which] = lo;
    }
}

__device__ __forceinline__ void packwf(const float* __restrict__ wf,
                                       unsigned* __restrict__ wffrag, int i)
{
    int kt = i / (21 * 32);
    int r = i % (21 * 32);
    int n8 = r / 32;
    int lane = r % 32;
    int gid = lane >> 2, tig = lane & 3;
    int n = n8 * 8 + gid;
#pragma unroll
    for (int which = 0; which < 2; which++) {
        int k0 = kt * 16 + which * 8 + tig * 2;
        float v0 = (n < NFUS) ? wf[(size_t)k0 * NFUS + n] : 0.f;
        float v1 = (n < NFUS) ? wf[(size_t)(k0 + 1) * NFUS + n] : 0.f;
        wffrag[(kt * 21 + n8) * 64 + lane * 2 + which] = bf16pair(v0, v1);
    }
}

__global__ void prep_all(const float* __restrict__ w_in, const float* __restrict__ w_out,
                         const float* __restrict__ wf,
                         unsigned* __restrict__ fin, unsigned* __restrict__ fout,
                         unsigned* __restrict__ ffw)
{
    int i = blockIdx.x * blockDim.x + threadIdx.x;
    if (i < 9216)              pack192(w_in,  fin,  i);
    else if (i < 18432)        pack192(w_out, fout, i - 9216);
    else if (i < 18432 + 8064) packwf(wf, ffw, i - 18432);
}

// ---------------------------------------------------------------------------
// Weight fusion (exact fp32): W_f = w_pw @ [w_off | w_mask]; last block: bias.
// ---------------------------------------------------------------------------
__global__ void fuse_wb(const float* __restrict__ wpw, const float* __restrict__ bpw,
                        const float* __restrict__ woff, const float* __restrict__ wmask,
                        const float* __restrict__ boff, const float* __restrict__ bmask,
                        float* __restrict__ wf, float* __restrict__ bf)
{
    int n = threadIdx.x;
    if (n >= NFUS) return;
    int blk = blockIdx.x;
    if (blk < Cc) {
        const float* wrow = wpw + (size_t)blk * Cc;
        float acc = 0.f;
        if (n < 108) {
            for (int o = 0; o < Cc; o++) acc = fmaf(wrow[o], woff[(size_t)o * 108 + n], acc);
        } else {
            int n2 = n - 108;
            for (int o = 0; o < Cc; o++) acc = fmaf(wrow[o], wmask[(size_t)o * 54 + n2], acc);
        }
        wf[(size_t)blk * NFUS + n] = acc;
    } else {
        float acc = (n < 108) ? boff[n] : bmask[n - 108];
        if (n < 108) {
            for (int o = 0; o < Cc; o++) acc = fmaf(bpw[o], woff[(size_t)o * 108 + n], acc);
        } else {
            int n2 = n - 108;
            for (int o = 0; o < Cc; o++) acc = fmaf(bpw[o], wmask[(size_t)o * 54 + n2], acc);
        }
        bf[n] = acc;
    }
}

// ---------------------------------------------------------------------------
// Smem-free bf16x3 GEMM: C[M,192] = A(fp32)[M,192] @ Wfrag + bias.
// ---------------------------------------------------------------------------
__global__ __launch_bounds__(256) void gemm_x3_direct(
    const float* __restrict__ A, const unsigned* __restrict__ wfrag,
    const float* __restrict__ bias, float* __restrict__ C)
{
    const int tid = threadIdx.x;
    const int wid = tid >> 5;
    const int lane = tid & 31;
    const int gid = lane >> 2;
    const int tig = lane & 3;
    const int bn8 = blockIdx.x * 8;
    const int bm = blockIdx.y * 256 + wid * 32;
    const uint2* wf2 = reinterpret_cast<const uint2*>(wfrag);

    float acc[2][8][4];
#pragma unroll
    for (int mt = 0; mt < 2; mt++)
#pragma unroll
        for (int nt = 0; nt < 8; nt++)
#pragma unroll
            for (int r = 0; r < 4; r++) acc[mt][nt][r] = 0.f;

    const float* ap0[2];
    const float* ap1[2];
#pragma unroll
    for (int mt = 0; mt < 2; mt++) {
        ap0[mt] = A + (size_t)(bm + mt * 16 + gid) * Cc + tig * 2;
        ap1[mt] = A + (size_t)(bm + mt * 16 + gid + 8) * Cc + tig * 2;
    }

    float2 av[2][4];
    auto loadA = [&](int kt) {
#pragma unroll
        for (int mt = 0; mt < 2; mt++) {
            av[mt][0] = *reinterpret_cast<const float2*>(ap0[mt] + kt * 16);
            av[mt][1] = *reinterpret_cast<const float2*>(ap1[mt] + kt * 16);
            av[mt][2] = *reinterpret_cast<const float2*>(ap0[mt] + kt * 16 + 8);
            av[mt][3] = *reinterpret_cast<const float2*>(ap1[mt] + kt * 16 + 8);
        }
    };

    loadA(0);
#pragma unroll
    for (int kt = 0; kt < 12; kt++) {
        unsigned ah[2][4], al[2][4];
#pragma unroll
        for (int mt = 0; mt < 2; mt++)
#pragma unroll
            for (int r = 0; r < 4; r++) {
                float v0 = av[mt][r].x, v1 = av[mt][r].y;
                unsigned hi = bf16pair(v0, v1);
                __nv_bfloat162 h2 = *reinterpret_cast<__nv_bfloat162*>(&hi);
                ah[mt][r] = hi;
                al[mt][r] = bf16pair(v0 - __bfloat162float(h2.x),
                                     v1 - __bfloat162float(h2.y));
            }
        if (kt < 11) loadA(kt + 1);

#pragma unroll
        for (int nt = 0; nt < 8; nt++) {
            uint2 bh = wf2[(size_t)((kt * 2 + 0) * 24 + bn8 + nt) * 32 + lane];
            uint2 bl = wf2[(size_t)((kt * 2 + 1) * 24 + bn8 + nt) * 32 + lane];
#pragma unroll
            for (int mt = 0; mt < 2; mt++) {
                mma_bf16(acc[mt][nt], ah[mt], bh.x, bh.y);
                mma_bf16(acc[mt][nt], ah[mt], bl.x, bl.y);
                mma_bf16(acc[mt][nt], al[mt], bh.x, bh.y);
            }
        }
    }

#pragma unroll
    for (int mt = 0; mt < 2; mt++) {
        int row0 = bm + mt * 16 + gid;
#pragma unroll
        for (int nt = 0; nt < 8; nt++) {
            int col = (bn8 + nt) * 8 + tig * 2;
            float2 bv = *reinterpret_cast<const float2*>(&bias[col]);
            float2 v0, v1;
            v0.x = acc[mt][nt][0] + bv.x; v0.y = acc[mt][nt][1] + bv.y;
            v1.x = acc[mt][nt][2] + bv.x; v1.y = acc[mt][nt][3] + bv.y;
            *reinterpret_cast<float2*>(&C[(size_t)row0 * Cc + col]) = v0;
            *reinterpret_cast<float2*>(&C[(size_t)(row0 + 8) * Cc + col]) = v1;
        }
    }
}

// ---------------------------------------------------------------------------
// Smem-free plain bf16 GEMM: C[M,162] = A(bf16)[M,192] @ WFfrag + bias.
// ---------------------------------------------------------------------------
__global__ __launch_bounds__(256) void gemm_plain_direct(
    const __nv_bfloat16* __restrict__ A, const unsigned* __restrict__ wffrag,
    const float* __restrict__ bias, float* __restrict__ C)
{
    const int tid = threadIdx.x;
    const int wid = tid >> 5;
    const int lane = tid & 31;
    const int gid = lane >> 2;
    const int tig = lane & 3;
    const int bn8 = blockIdx.x * 7;
    const int bm = blockIdx.y * 256 + wid * 32;
    const uint2* wf2 = reinterpret_cast<const uint2*>(wffrag);

    float acc[2][7][4];
#pragma unroll
    for (int mt = 0; mt < 2; mt++)
#pragma unroll
        for (int nt = 0; nt < 7; nt++)
#pragma unroll
            for (int r = 0; r < 4; r++) acc[mt][nt][r] = 0.f;

    const __nv_bfloat16* ap0[2];
    const __nv_bfloat16* ap1[2];
#pragma unroll
    for (int mt = 0; mt < 2; mt++) {
        ap0[mt] = A + (size_t)(bm + mt * 16 + gid) * Cc + tig * 2;
        ap1[mt] = A + (size_t)(bm + mt * 16 + gid + 8) * Cc + tig * 2;
    }

    unsigned ar[2][4];
    auto loadA = [&](int kt) {
#pragma unroll
        for (int mt = 0; mt < 2; mt++) {
            ar[mt][0] = *reinterpret_cast<const unsigned*>(ap0[mt] + kt * 16);
            ar[mt][1] = *reinterpret_cast<const unsigned*>(ap1[mt] + kt * 16);
            ar[mt][2] = *reinterpret_cast<const unsigned*>(ap0[mt] + kt * 16 + 8);
            ar[mt][3] = *reinterpret_cast<const unsigned*>(ap1[mt] + kt * 16 + 8);
        }
    };

    loadA(0);
#pragma unroll
    for (int kt = 0; kt < 12; kt++) {
        unsigned a0[2][4];
#pragma unroll
        for (int mt = 0; mt < 2; mt++)
#pragma unroll
            for (int r = 0; r < 4; r++) a0[mt][r] = ar[mt][r];
        if (kt < 11) loadA(kt + 1);

#pragma unroll
        for (int nt = 0; nt < 7; nt++) {
            uint2 bh = wf2[(size_t)(kt * 21 + bn8 + nt) * 32 + lane];
#pragma unroll
            for (int mt = 0; mt < 2; mt++)
                mma_bf16(acc[mt][nt], a0[mt], bh.x, bh.y);
        }
    }

#pragma unroll
    for (int mt = 0; mt < 2; mt++) {
        int row0 = bm + mt * 16 + gid;
#pragma unroll
        for (int nt = 0; nt < 7; nt++) {
            int col = (bn8 + nt) * 8 + tig * 2;
            if (col < NFUS) {
                float b0 = bias[col];
                C[(size_t)row0 * NFUS + col]       = acc[mt][nt][0] + b0;
                C[(size_t)(row0 + 8) * NFUS + col] = acc[mt][nt][2] + b0;
            }
            if (col + 1 < NFUS) {
                float b1 = bias[col + 1];
                C[(size_t)row0 * NFUS + col + 1]       = acc[mt][nt][1] + b1;
                C[(size_t)(row0 + 8) * NFUS + col + 1] = acc[mt][nt][3] + b1;
            }
        }
    }
}

// ---------------------------------------------------------------------------
// Depthwise 3x3 + bias + SiLU, register-blocked, bf16 output.
// ---------------------------------------------------------------------------
__global__ __launch_bounds__(256) void dw_silu(
    const float4* __restrict__ x, const float4* __restrict__ wdw,
    const float4* __restrict__ bdw, __nv_bfloat16* __restrict__ out)
{
    const int C4 = Cc / 4;        // 48
    const int RW = Wd / 4;
    const size_t total = (size_t)(M_PIX / 4) * C4;
    size_t idx = (size_t)blockIdx.x * blockDim.x + threadIdx.x;
    if (idx >= total) return;

    int c4 = (int)(idx % C4);
    int run = (int)(idx / C4);
    int w0 = (run % RW) * 4;
    int h = (run / RW) % Hh;
    int b = run / (RW * Hh);

    float4 bias = bdw[c4];
    float4 acc[4] = {bias, bias, bias, bias};
    const float4 z = make_float4(0.f, 0.f, 0.f, 0.f);

#pragma unroll
    for (int ky = 0; ky < 3; ky++) {
        int hy = h + ky - 1;
        if (hy < 0 || hy >= Hh) continue;
        const float4* row = x + ((size_t)(b * Hh + hy) * Wd) * C4 + c4;
        float4 xv[6];
        xv[0] = (w0 > 0) ? row[(size_t)(w0 - 1) * C4] : z;
#pragma unroll
        for (int t = 0; t < 4; t++) xv[1 + t] = row[(size_t)(w0 + t) * C4];
        xv[5] = (w0 + 4 < Wd) ? row[(size_t)(w0 + 4) * C4] : z;

        float4 wt[3];
#pragma unroll
        for (int kx = 0; kx < 3; kx++) wt[kx] = wdw[(ky * 3 + kx) * C4 + c4];

#pragma unroll
        for (int ow = 0; ow < 4; ow++) {
#pragma unroll
            for (int kx = 0; kx < 3; kx++) {
                float4 v = xv[ow + kx];
                acc[ow].x = fmaf(v.x, wt[kx].x, acc[ow].x);
                acc[ow].y = fmaf(v.y, wt[kx].y, acc[ow].y);
                acc[ow].z = fmaf(v.z, wt[kx].z, acc[ow].z);
                acc[ow].w = fmaf(v.w, wt[kx].w, acc[ow].w);
            }
        }
    }

#pragma unroll
    for (int ow = 0; ow < 4; ow++) {
        float4 a = acc[ow];
        a.x = a.x / (1.f + expf(-a.x));
        a.y = a.y / (1.f + expf(-a.y));
        a.z = a.z / (1.f + expf(-a.z));
        a.w = a.w / (1.f + expf(-a.w));
        uint2 pk;
        pk.x = bf16pair(a.x, a.y);
        pk.y = bf16pair(a.z, a.w);
        *reinterpret_cast<uint2*>(
            &out[((size_t)(b * Hh + h) * Wd + (w0 + ow)) * Cc + c4 * 4]) = pk;
    }
}

// ---------------------------------------------------------------------------
// FUSED: softmax + deformable bilinear sampling + final GEMM (bf16x3).
// Per group: threads 0-63 compute per-(px,tap) folded weights {a*(1-fh)(1-fw),...}
// + base smem index WHILE threads 64-255 stage the x_proj window. Sampling
// inner loop is then 2 broadcast LDS + 4 LDS.64 + 8 FMA per tap.
// smem: xs 21632 + tapw 9216 + tapi 2304 + As 49152 = 82304 B (2 blocks/SM).
// ---------------------------------------------------------------------------
#define SM_XS    0
#define SM_TW    21632
#define SM_TI    30848
#define SM_AS    33152
#define SM_TOTAL 82304

__global__ __launch_bounds__(256) void deform_gemm(
    const float* __restrict__ xproj, const float* __restrict__ offmsk,
    const unsigned* __restrict__ wfrag, const float* __restrict__ bias,
    float* __restrict__ out)
{
    extern __shared__ char smem_raw[];
    float2* xs = reinterpret_cast<float2*>(smem_raw + SM_XS);          // [169][16]
    float4* tapw = reinterpret_cast<float4*>(smem_raw + SM_TW);        // [64][9]
    int* tapi = reinterpret_cast<int*>(smem_raw + SM_TI);              // [64][9]
    unsigned* As = reinterpret_cast<unsigned*>(smem_raw + SM_AS);      // [2][12][4][32][4]

    const int tile = blockIdx.x;
    const int tid = threadIdx.x;
    const int wid = tid >> 5;
    const int lane = tid & 31;

    const int b  = tile >> 8;
    const int ty = (tile >> 4) & 15;
    const int tx = tile & 15;
    const int h0 = ty * 8, w0 = tx * 8;

    const int half = lane >> 4;
    const int ch = lane & 15;

    for (int g = 0; g < Gg; g++) {
        if (g) __syncthreads();   // previous group done reading xs/meta

        if (tid < 64) {
            // --- meta: softmax + folded bilinear weights for pixel tid ---
            int py = tid >> 3, px = tid & 7;
            int h = h0 + py, w = w0 + px;
            const float* om = offmsk + (((size_t)(b * Hh + h)) * Wd + w) * NFUS;
            float m[KK2], mx = -1e30f;
#pragma unroll
            for (int k = 0; k < KK2; k++) { m[k] = om[108 + g * KK2 + k]; mx = fmaxf(mx, m[k]); }
            float sum = 0.f;
#pragma unroll
            for (int k = 0; k < KK2; k++) { m[k] = expf(m[k] - mx); sum += m[k]; }
            float inv = 1.f / sum;
#pragma unroll
            for (int k = 0; k < KK2; k++) {
                float a = m[k] * inv;
                float ph = (float)h + (float)(k / 3 - 1) + om[g * 18 + 2 * k]     * 0.1f;
                float pw = (float)w + (float)(k % 3 - 1) + om[g * 18 + 2 * k + 1] * 0.1f;
                ph = fminf(fmaxf(ph, 0.f), (float)(Hh - 1));
                pw = fminf(fmaxf(pw, 0.f), (float)(Wd - 1));
                int hf = (int)ph;
                int wf = (int)pw;
                float fh = ph - (float)hf;
                float fw = pw - (float)wf;
                int hl = min(max(hf - (h0 - 2), 0), 11);
                int wl = min(max(wf - (w0 - 2), 0), 11);
                float4 wv;
                wv.x = a * (1.f - fh) * (1.f - fw);
                wv.y = a * (1.f - fh) * fw;
                wv.z = a * fh * (1.f - fw);
                wv.w = a * fh * fw;
                tapw[tid * KK2 + k] = wv;
                tapi[tid * KK2 + k] = (hl * 13 + wl) * 16;
            }
        } else {
            // --- stage 13x13x32 window of group g (threads 64..255) ---
            for (int idx = tid - 64; idx < 13 * 13 * 8; idx += 192) {
                int cell = idx >> 3;
                int c4 = idx & 7;
                int hi = cell / 13, wi = cell % 13;
                int row = min(max(h0 - 2 + hi, 0), Hh - 1);
                int col = min(max(w0 - 2 + wi, 0), Wd - 1);
                float4 v = *reinterpret_cast<const float4*>(
                    &xproj[(((size_t)(b * Hh + row)) * Wd + col) * Cc + g * GC + c4 * 4]);
                xs[cell * 16 + c4 * 2]     = make_float2(v.x, v.y);
                xs[cell * 16 + c4 * 2 + 1] = make_float2(v.z, v.w);
            }
        }
        __syncthreads();

        // --- sample + write fragment-major bf16 hi/lo into As ---
        const int ktile = g * 2 + (ch >> 3);
        const int tigw = ch & 3;
        const int khalf = (ch >> 2) & 1;
#pragma unroll
        for (int pass = 0; pass < 4; pass++) {
            int p = wid * 8 + pass * 2 + half;
            float2 acc = make_float2(0.f, 0.f);
#pragma unroll
            for (int k = 0; k < KK2; k++) {
                float4 wv = tapw[p * KK2 + k];
                int c00 = tapi[p * KK2 + k] + ch;
                float2 v00 = xs[c00];
                float2 v01 = xs[c00 + 16];
                float2 v10 = xs[c00 + 208];
                float2 v11 = xs[c00 + 224];
                acc.x = fmaf(wv.x, v00.x, acc.x);
                acc.x = fmaf(wv.y, v01.x, acc.x);
                acc.x = fmaf(wv.z, v10.x, acc.x);
                acc.x = fmaf(wv.w, v11.x, acc.x);
                acc.y = fmaf(wv.x, v00.y, acc.y);
                acc.y = fmaf(wv.y, v01.y, acc.y);
                acc.y = fmaf(wv.z, v10.y, acc.y);
                acc.y = fmaf(wv.w, v11.y, acc.y);
            }
            int mb = p >> 4;
            int gp = p & 7;
            int half_r = (p >> 3) & 1;
            int reg = half_r + 2 * khalf;
            unsigned hi = bf16pair(acc.x, acc.y);
            __nv_bfloat162 h2 = *reinterpret_cast<__nv_bfloat162*>(&hi);
            unsigned lo = bf16pair(acc.x - __bfloat162float(h2.x),
                                   acc.y - __bfloat162float(h2.y));
            As[((0 * 12 + ktile) * 4 + mb) * 128 + (gp * 4 + tigw) * 4 + reg] = hi;
            As[((1 * 12 + ktile) * 4 + mb) * 128 + (gp * 4 + tigw) * 4 + reg] = lo;
        }
    }
    __syncthreads();

    // ================= GEMM phase: [64,192] @ [192,192] bf16x3 =================
    const uint2* wf2 = reinterpret_cast<const uint2*>(wfrag);
    float acc[4][3][4];
#pragma unroll
    for (int mt = 0; mt < 4; mt++)
#pragma unroll
        for (int nt = 0; nt < 3; nt++)
#pragma unroll
            for (int r = 0; r < 4; r++) acc[mt][nt][r] = 0.f;

    uint2 bh[2][3], bl[2][3];
    auto loadB = [&](int kt, int pb) {
#pragma unroll
        for (int nt = 0; nt < 3; nt++) {
            int n8 = wid * 3 + nt;
            bh[pb][nt] = wf2[((kt * 2 + 0) * 24 + n8) * 32 + lane];
            bl[pb][nt] = wf2[((kt * 2 + 1) * 24 + n8) * 32 + lane];
        }
    };
    loadB(0, 0);
    int pb = 0;
#pragma unroll
    for (int kt = 0; kt < 12; kt++) {
        if (kt < 11) loadB(kt + 1, pb ^ 1);
        unsigned ah[4][4], al[4][4];
#pragma unroll
        for (int mb = 0; mb < 4; mb++) {
            uint4 u = *reinterpret_cast<const uint4*>(
                &As[((0 * 12 + kt) * 4 + mb) * 128 + lane * 4]);
            ah[mb][0] = u.x; ah[mb][1] = u.y; ah[mb][2] = u.z; ah[mb][3] = u.w;
            uint4 v = *reinterpret_cast<const uint4*>(
                &As[((1 * 12 + kt) * 4 + mb) * 128 + lane * 4]);
            al[mb][0] = v.x; al[mb][1] = v.y; al[mb][2] = v.z; al[mb][3] = v.w;
        }
#pragma unroll
        for (int mt = 0; mt < 4; mt++)
#pragma unroll
            for (int nt = 0; nt < 3; nt++) {
                mma_bf16(acc[mt][nt], ah[mt], bh[pb][nt].x, bh[pb][nt].y);
                mma_bf16(acc[mt][nt], ah[mt], bl[pb][nt].x, bl[pb][nt].y);
                mma_bf16(acc[mt][nt], al[mt], bh[pb][nt].x, bh[pb][nt].y);
            }
        pb ^= 1;
    }

    const int gid = lane >> 2;
    const int tig = lane & 3;
#pragma unroll
    for (int mt = 0; mt < 4; mt++) {
#pragma unroll
        for (int rr = 0; rr < 2; rr++) {
            int p = mt * 16 + rr * 8 + gid;
            size_t pix = ((size_t)(b * Hh + h0 + (p >> 3)) * Wd + w0 + (p & 7));
#pragma unroll
            for (int nt = 0; nt < 3; nt++) {
                int n = (wid * 3 + nt) * 8 + tig * 2;
                float2 v;
                v.x = acc[mt][nt][rr * 2 + 0] + bias[n];
                v.y = acc[mt][nt][rr * 2 + 1] + bias[n + 1];
                *reinterpret_cast<float2*>(&out[pix * Cc + n]) = v;
            }
        }
    }
}

// ---------------------------------------------------------------------------
// Launch
// ---------------------------------------------------------------------------
extern "C" void kernel_launch(void* const* d_in, const int* in_sizes, int n_in,
                              void* d_out, int out_size)
{
    const float* x      = (const float*)d_in[0];
    const float* w_in   = (const float*)d_in[1];
    const float* b_in   = (const float*)d_in[2];
    const float* w_dw   = (const float*)d_in[3];
    const float* b_dw   = (const float*)d_in[4];
    const float* w_pw   = (const float*)d_in[5];
    const float* b_pw   = (const float*)d_in[6];
    const float* w_off  = (const float*)d_in[7];
    const float* b_off  = (const float*)d_in[8];
    const float* w_mask = (const float*)d_in[9];
    const float* b_mask = (const float*)d_in[10];
    const float* w_out  = (const float*)d_in[11];
    const float* b_out  = (const float*)d_in[12];
    float* out = (float*)d_out;

    float *xproj, *tmp, *offmsk, *wf, *bfu;
    unsigned *wfin, *wfout, *wff;
    cudaGetSymbolAddress((void**)&xproj,  g_xproj);
    cudaGetSymbolAddress((void**)&tmp,    g_tmp);
    cudaGetSymbolAddress((void**)&offmsk, g_offmsk);
    cudaGetSymbolAddress((void**)&wf,     g_wf);
    cudaGetSymbolAddress((void**)&bfu,    g_bfuse);
    cudaGetSymbolAddress((void**)&wfin,   g_wfrag_in);
    cudaGetSymbolAddress((void**)&wfout,  g_wfrag_out);
    cudaGetSymbolAddress((void**)&wff,    g_wffrag);

    cudaFuncSetAttribute(deform_gemm, cudaFuncAttributeMaxDynamicSharedMemorySize, SM_TOTAL);

    // 0. weight prep: fuse pw into offset/mask (fp32), then pack all fragments
    fuse_wb<<<Cc + 1, 192>>>(w_pw, b_pw, w_off, w_mask, b_off, b_mask, wf, bfu);
    prep_all<<<(26496 + 255) / 256, 256>>>(w_in, w_out, wf, wfin, wfout, wff);
    // 1. x_proj = x @ w_in + b_in  (bf16x3, smem-free)
    gemm_x3_direct<<<dim3(3, M_PIX / 256), 256>>>(x, wfin, b_in, xproj);
    // 2. depthwise 3x3 + SiLU -> bf16 tmp
    {
        size_t n = (size_t)(M_PIX / 4) * (Cc / 4);
        dw_silu<<<(unsigned)((n + 255) / 256), 256>>>(
            (const float4*)x, (const float4*)w_dw, (const float4*)b_dw,
            (__nv_bfloat16*)tmp);
    }
    // 3. [offsets|mask] = dwout_bf16 @ W_f + b_f  (plain bf16, smem-free)
    gemm_plain_direct<<<dim3(3, M_PIX / 256), 256>>>(
        (const __nv_bfloat16*)tmp, wff, bfu, offmsk);
    // 4+5. fused softmax + deformable sampling + final GEMM -> out
    deform_gemm<<<2048, 256, SM_TOTAL>>>(xproj, offmsk, wfout, b_out, out);
}

// round 8
// speedup vs baseline: 1.2967x; 1.0302x over previous
#include <cuda_runtime.h>
#include <cuda_bf16.h>
#include <cuda_fp16.h>
#include <math.h>

#define Bn   8
#define Hh   128
#define Wd   128
#define Cc   192
#define Gg   6
#define GC   32
#define KK2  9
#define NFUS 162     // 108 offsets + 54 mask logits
#define M_PIX (Bn*Hh*Wd)   // 131072

// Scratch (device globals — no runtime allocation allowed)
__device__ __half g_xproj [(size_t)M_PIX * Cc];      // x_proj as fp16
__device__ float g_tmp   [(size_t)M_PIX * Cc / 2];   // dw output as bf16
__device__ float g_offmsk[(size_t)M_PIX * NFUS];
__device__ float g_wf    [Cc * NFUS];
__device__ float g_bfuse [NFUS];
__device__ unsigned g_wfrag_in [12 * 2 * 24 * 64];   // w_in  fragment-major bf16 hi/lo
__device__ unsigned g_wfrag_out[12 * 2 * 24 * 64];   // w_out fragment-major bf16 hi/lo
__device__ unsigned g_wffrag   [12 * 21 * 64];       // fused W fragment-major bf16 (hi), N padded->168

// ---------------------------------------------------------------------------
// bf16 helpers
// ---------------------------------------------------------------------------
__device__ __forceinline__ unsigned bf16pair(float a, float b) {
    __nv_bfloat162 t = __floats2bfloat162_rn(a, b);   // a -> low half (even k)
    return *reinterpret_cast<unsigned*>(&t);
}
__device__ __forceinline__ void mma_bf16(float* d, const unsigned* a, unsigned b0, unsigned b1) {
    asm volatile(
        "mma.sync.aligned.m16n8k16.row.col.f32.bf16.bf16.f32 "
        "{%0,%1,%2,%3}, {%4,%5,%6,%7}, {%8,%9}, {%0,%1,%2,%3};\n"
        : "+f"(d[0]), "+f"(d[1]), "+f"(d[2]), "+f"(d[3])
        : "r"(a[0]), "r"(a[1]), "r"(a[2]), "r"(a[3]), "r"(b0), "r"(b1));
}

// ---------------------------------------------------------------------------
// Weight packing (one kernel for all three packs)
// ---------------------------------------------------------------------------
__device__ __forceinline__ void pack192(const float* __restrict__ w,
                                        unsigned* __restrict__ wfrag, int i)
{
    int kt = i / (24 * 32);
    int r = i % (24 * 32);
    int n8 = r / 32;
    int lane = r % 32;
    int gid = lane >> 2, tig = lane & 3;
    int n = n8 * 8 + gid;
#pragma unroll
    for (int which = 0; which < 2; which++) {
        int k0 = kt * 16 + which * 8 + tig * 2;
        float v0 = w[(size_t)k0 * Cc + n];
        float v1 = w[(size_t)(k0 + 1) * Cc + n];
        unsigned hi = bf16pair(v0, v1);
        __nv_bfloat162 h2 = *reinterpret_cast<__nv_bfloat162*>(&hi);
        unsigned lo = bf16pair(v0 - __bfloat162float(h2.x), v1 - __bfloat162float(h2.y));
        wfrag[((kt * 2 + 0) * 24 + n8) * 64 + lane * 2 + which] = hi;
        wfrag[((kt * 2 + 1) * 24 + n8) * 64 + lane * 2 + which] = lo;
    }
}

__device__ __forceinline__ void packwf(const float* __restrict__ wf,
                                       unsigned* __restrict__ wffrag, int i)
{
    int kt = i / (21 * 32);
    int r = i % (21 * 32);
    int n8 = r / 32;
    int lane = r % 32;
    int gid = lane >> 2, tig = lane & 3;
    int n = n8 * 8 + gid;
#pragma unroll
    for (int which = 0; which < 2; which++) {
        int k0 = kt * 16 + which * 8 + tig * 2;
        float v0 = (n < NFUS) ? wf[(size_t)k0 * NFUS + n] : 0.f;
        float v1 = (n < NFUS) ? wf[(size_t)(k0 + 1) * NFUS + n] : 0.f;
        wffrag[(kt * 21 + n8) * 64 + lane * 2 + which] = bf16pair(v0, v1);
    }
}

__global__ void prep_all(const float* __restrict__ w_in, const float* __restrict__ w_out,
                         const float* __restrict__ wf,
                         unsigned* __restrict__ fin, unsigned* __restrict__ fout,
                         unsigned* __restrict__ ffw)
{
    int i = blockIdx.x * blockDim.x + threadIdx.x;
    if (i < 9216)              pack192(w_in,  fin,  i);
    else if (i < 18432)        pack192(w_out, fout, i - 9216);
    else if (i < 18432 + 8064) packwf(wf, ffw, i - 18432);
}

// ---------------------------------------------------------------------------
// Weight fusion (exact fp32): W_f = w_pw @ [w_off | w_mask]; last block: bias.
// ---------------------------------------------------------------------------
__global__ void fuse_wb(const float* __restrict__ wpw, const float* __restrict__ bpw,
                        const float* __restrict__ woff, const float* __restrict__ wmask,
                        const float* __restrict__ boff, const float* __restrict__ bmask,
                        float* __restrict__ wf, float* __restrict__ bf)
{
    int n = threadIdx.x;
    if (n >= NFUS) return;
    int blk = blockIdx.x;
    if (blk < Cc) {
        const float* wrow = wpw + (size_t)blk * Cc;
        float acc = 0.f;
        if (n < 108) {
            for (int o = 0; o < Cc; o++) acc = fmaf(wrow[o], woff[(size_t)o * 108 + n], acc);
        } else {
            int n2 = n - 108;
            for (int o = 0; o < Cc; o++) acc = fmaf(wrow[o], wmask[(size_t)o * 54 + n2], acc);
        }
        wf[(size_t)blk * NFUS + n] = acc;
    } else {
        float acc = (n < 108) ? boff[n] : bmask[n - 108];
        if (n < 108) {
            for (int o = 0; o < Cc; o++) acc = fmaf(bpw[o], woff[(size_t)o * 108 + n], acc);
        } else {
            int n2 = n - 108;
            for (int o = 0; o < Cc; o++) acc = fmaf(bpw[o], wmask[(size_t)o * 54 + n2], acc);
        }
        bf[n] = acc;
    }
}

// ---------------------------------------------------------------------------
// Smem-free bf16x3 GEMM, full N=192 per block, fp16 output.
// Grid M/128, block 256 (8 warps: 4 along M x 2 along N). Warp tile 32x96.
// A rows converted to bf16 hi/lo exactly once.
// ---------------------------------------------------------------------------
__global__ __launch_bounds__(256) void gemm_x3_fp16out(
    const float* __restrict__ A, const unsigned* __restrict__ wfrag,
    const float* __restrict__ bias, __half* __restrict__ C)
{
    const int tid = threadIdx.x;
    const int wid = tid >> 5;
    const int lane = tid & 31;
    const int gid = lane >> 2;
    const int tig = lane & 3;
    const int bm = blockIdx.x * 128 + (wid & 3) * 32;
    const int n8base = (wid >> 2) * 12;          // 2 n-halves of 96 cols
    const uint2* wf2 = reinterpret_cast<const uint2*>(wfrag);

    float acc[2][12][4];
#pragma unroll
    for (int mt = 0; mt < 2; mt++)
#pragma unroll
        for (int nt = 0; nt < 12; nt++)
#pragma unroll
            for (int r = 0; r < 4; r++) acc[mt][nt][r] = 0.f;

    const float* ap0[2];
    const float* ap1[2];
#pragma unroll
    for (int mt = 0; mt < 2; mt++) {
        ap0[mt] = A + (size_t)(bm + mt * 16 + gid) * Cc + tig * 2;
        ap1[mt] = A + (size_t)(bm + mt * 16 + gid + 8) * Cc + tig * 2;
    }

    float2 av[2][4];
    auto loadA = [&](int kt) {
#pragma unroll
        for (int mt = 0; mt < 2; mt++) {
            av[mt][0] = *reinterpret_cast<const float2*>(ap0[mt] + kt * 16);
            av[mt][1] = *reinterpret_cast<const float2*>(ap1[mt] + kt * 16);
            av[mt][2] = *reinterpret_cast<const float2*>(ap0[mt] + kt * 16 + 8);
            av[mt][3] = *reinterpret_cast<const float2*>(ap1[mt] + kt * 16 + 8);
        }
    };

    loadA(0);
#pragma unroll
    for (int kt = 0; kt < 12; kt++) {
        unsigned ah[2][4], al[2][4];
#pragma unroll
        for (int mt = 0; mt < 2; mt++)
#pragma unroll
            for (int r = 0; r < 4; r++) {
                float v0 = av[mt][r].x, v1 = av[mt][r].y;
                unsigned hi = bf16pair(v0, v1);
                __nv_bfloat162 h2 = *reinterpret_cast<__nv_bfloat162*>(&hi);
                ah[mt][r] = hi;
                al[mt][r] = bf16pair(v0 - __bfloat162float(h2.x),
                                     v1 - __bfloat162float(h2.y));
            }
        if (kt < 11) loadA(kt + 1);

#pragma unroll
        for (int nt = 0; nt < 12; nt++) {
            uint2 bh = wf2[(size_t)((kt * 2 + 0) * 24 + n8base + nt) * 32 + lane];
            uint2 bl = wf2[(size_t)((kt * 2 + 1) * 24 + n8base + nt) * 32 + lane];
#pragma unroll
            for (int mt = 0; mt < 2; mt++) {
                mma_bf16(acc[mt][nt], ah[mt], bh.x, bh.y);
                mma_bf16(acc[mt][nt], ah[mt], bl.x, bl.y);
                mma_bf16(acc[mt][nt], al[mt], bh.x, bh.y);
            }
        }
    }

#pragma unroll
    for (int mt = 0; mt < 2; mt++) {
        int row0 = bm + mt * 16 + gid;
#pragma unroll
        for (int nt = 0; nt < 12; nt++) {
            int col = (n8base + nt) * 8 + tig * 2;
            float2 bv = *reinterpret_cast<const float2*>(&bias[col]);
            __half2 h0 = __floats2half2_rn(acc[mt][nt][0] + bv.x, acc[mt][nt][1] + bv.y);
            __half2 h1 = __floats2half2_rn(acc[mt][nt][2] + bv.x, acc[mt][nt][3] + bv.y);
            *reinterpret_cast<__half2*>(&C[(size_t)row0 * Cc + col]) = h0;
            *reinterpret_cast<__half2*>(&C[(size_t)(row0 + 8) * Cc + col]) = h1;
        }
    }
}

// ---------------------------------------------------------------------------
// Smem-free plain bf16 GEMM: C[M,162] = A(bf16)[M,192] @ WFfrag + bias.
// ---------------------------------------------------------------------------
__global__ __launch_bounds__(256) void gemm_plain_direct(
    const __nv_bfloat16* __restrict__ A, const unsigned* __restrict__ wffrag,
    const float* __restrict__ bias, float* __restrict__ C)
{
    const int tid = threadIdx.x;
    const int wid = tid >> 5;
    const int lane = tid & 31;
    const int gid = lane >> 2;
    const int tig = lane & 3;
    const int bn8 = blockIdx.x * 7;
    const int bm = blockIdx.y * 256 + wid * 32;
    const uint2* wf2 = reinterpret_cast<const uint2*>(wffrag);

    float acc[2][7][4];
#pragma unroll
    for (int mt = 0; mt < 2; mt++)
#pragma unroll
        for (int nt = 0; nt < 7; nt++)
#pragma unroll
            for (int r = 0; r < 4; r++) acc[mt][nt][r] = 0.f;

    const __nv_bfloat16* ap0[2];
    const __nv_bfloat16* ap1[2];
#pragma unroll
    for (int mt = 0; mt < 2; mt++) {
        ap0[mt] = A + (size_t)(bm + mt * 16 + gid) * Cc + tig * 2;
        ap1[mt] = A + (size_t)(bm + mt * 16 + gid + 8) * Cc + tig * 2;
    }

    unsigned ar[2][4];
    auto loadA = [&](int kt) {
#pragma unroll
        for (int mt = 0; mt < 2; mt++) {
            ar[mt][0] = *reinterpret_cast<const unsigned*>(ap0[mt] + kt * 16);
            ar[mt][1] = *reinterpret_cast<const unsigned*>(ap1[mt] + kt * 16);
            ar[mt][2] = *reinterpret_cast<const unsigned*>(ap0[mt] + kt * 16 + 8);
            ar[mt][3] = *reinterpret_cast<const unsigned*>(ap1[mt] + kt * 16 + 8);
        }
    };

    loadA(0);
#pragma unroll
    for (int kt = 0; kt < 12; kt++) {
        unsigned a0[2][4];
#pragma unroll
        for (int mt = 0; mt < 2; mt++)
#pragma unroll
            for (int r = 0; r < 4; r++) a0[mt][r] = ar[mt][r];
        if (kt < 11) loadA(kt + 1);

#pragma unroll
        for (int nt = 0; nt < 7; nt++) {
            uint2 bh = wf2[(size_t)(kt * 21 + bn8 + nt) * 32 + lane];
#pragma unroll
            for (int mt = 0; mt < 2; mt++)
                mma_bf16(acc[mt][nt], a0[mt], bh.x, bh.y);
        }
    }

#pragma unroll
    for (int mt = 0; mt < 2; mt++) {
        int row0 = bm + mt * 16 + gid;
#pragma unroll
        for (int nt = 0; nt < 7; nt++) {
            int col = (bn8 + nt) * 8 + tig * 2;
            if (col < NFUS) {
                float b0 = bias[col];
                C[(size_t)row0 * NFUS + col]       = acc[mt][nt][0] + b0;
                C[(size_t)(row0 + 8) * NFUS + col] = acc[mt][nt][2] + b0;
            }
            if (col + 1 < NFUS) {
                float b1 = bias[col + 1];
                C[(size_t)row0 * NFUS + col + 1]       = acc[mt][nt][1] + b1;
                C[(size_t)(row0 + 8) * NFUS + col + 1] = acc[mt][nt][3] + b1;
            }
        }
    }
}

// ---------------------------------------------------------------------------
// Depthwise 3x3 + bias + SiLU, register-blocked, bf16 output.
// ---------------------------------------------------------------------------
__global__ __launch_bounds__(256) void dw_silu(
    const float4* __restrict__ x, const float4* __restrict__ wdw,
    const float4* __restrict__ bdw, __nv_bfloat16* __restrict__ out)
{
    const int C4 = Cc / 4;        // 48
    const int RW = Wd / 4;
    const size_t total = (size_t)(M_PIX / 4) * C4;
    size_t idx = (size_t)blockIdx.x * blockDim.x + threadIdx.x;
    if (idx >= total) return;

    int c4 = (int)(idx % C4);
    int run = (int)(idx / C4);
    int w0 = (run % RW) * 4;
    int h = (run / RW) % Hh;
    int b = run / (RW * Hh);

    float4 bias = bdw[c4];
    float4 acc[4] = {bias, bias, bias, bias};
    const float4 z = make_float4(0.f, 0.f, 0.f, 0.f);

#pragma unroll
    for (int ky = 0; ky < 3; ky++) {
        int hy = h + ky - 1;
        if (hy < 0 || hy >= Hh) continue;
        const float4* row = x + ((size_t)(b * Hh + hy) * Wd) * C4 + c4;
        float4 xv[6];
        xv[0] = (w0 > 0) ? row[(size_t)(w0 - 1) * C4] : z;
#pragma unroll
        for (int t = 0; t < 4; t++) xv[1 + t] = row[(size_t)(w0 + t) * C4];
        xv[5] = (w0 + 4 < Wd) ? row[(size_t)(w0 + 4) * C4] : z;

        float4 wt[3];
#pragma unroll
        for (int kx = 0; kx < 3; kx++) wt[kx] = wdw[(ky * 3 + kx) * C4 + c4];

#pragma unroll
        for (int ow = 0; ow < 4; ow++) {
#pragma unroll
            for (int kx = 0; kx < 3; kx++) {
                float4 v = xv[ow + kx];
                acc[ow].x = fmaf(v.x, wt[kx].x, acc[ow].x);
                acc[ow].y = fmaf(v.y, wt[kx].y, acc[ow].y);
                acc[ow].z = fmaf(v.z, wt[kx].z, acc[ow].z);
                acc[ow].w = fmaf(v.w, wt[kx].w, acc[ow].w);
            }
        }
    }

#pragma unroll
    for (int ow = 0; ow < 4; ow++) {
        float4 a = acc[ow];
        a.x = a.x / (1.f + expf(-a.x));
        a.y = a.y / (1.f + expf(-a.y));
        a.z = a.z / (1.f + expf(-a.z));
        a.w = a.w / (1.f + expf(-a.w));
        uint2 pk;
        pk.x = bf16pair(a.x, a.y);
        pk.y = bf16pair(a.z, a.w);
        *reinterpret_cast<uint2*>(
            &out[((size_t)(b * Hh + h) * Wd + (w0 + ow)) * Cc + c4 * 4]) = pk;
    }
}

// ---------------------------------------------------------------------------
// FUSED: softmax + deformable bilinear sampling (fp16 window) + final GEMM.
// smem: xs 10816 + tapw 9216 + tapi 2304 + As 49152 = 71488 B.
// ---------------------------------------------------------------------------
#define SM_XS    0
#define SM_TW    10816
#define SM_TI    20032
#define SM_AS    22336
#define SM_TOTAL 71488

__global__ __launch_bounds__(256) void deform_gemm(
    const __half* __restrict__ xproj, const float* __restrict__ offmsk,
    const unsigned* __restrict__ wfrag, const float* __restrict__ bias,
    float* __restrict__ out)
{
    extern __shared__ char smem_raw[];
    __half2* xs = reinterpret_cast<__half2*>(smem_raw + SM_XS);        // [169][16]
    float4* tapw = reinterpret_cast<float4*>(smem_raw + SM_TW);        // [64][9]
    int* tapi = reinterpret_cast<int*>(smem_raw + SM_TI);              // [64][9]
    unsigned* As = reinterpret_cast<unsigned*>(smem_raw + SM_AS);      // [2][12][4][32][4]

    const int tile = blockIdx.x;
    const int tid = threadIdx.x;
    const int wid = tid >> 5;
    const int lane = tid & 31;

    const int b  = tile >> 8;
    const int ty = (tile >> 4) & 15;
    const int tx = tile & 15;
    const int h0 = ty * 8, w0 = tx * 8;

    const int half = lane >> 4;
    const int ch = lane & 15;

    for (int g = 0; g < Gg; g++) {
        if (g) __syncthreads();   // previous group done reading xs/meta

        if (tid < 64) {
            // --- meta: softmax + folded bilinear weights for pixel tid ---
            int py = tid >> 3, px = tid & 7;
            int h = h0 + py, w = w0 + px;
            const float* om = offmsk + (((size_t)(b * Hh + h)) * Wd + w) * NFUS;
            float m[KK2], mx = -1e30f;
#pragma unroll
            for (int k = 0; k < KK2; k++) { m[k] = om[108 + g * KK2 + k]; mx = fmaxf(mx, m[k]); }
            float sum = 0.f;
#pragma unroll
            for (int k = 0; k < KK2; k++) { m[k] = expf(m[k] - mx); sum += m[k]; }
            float inv = 1.f / sum;
#pragma unroll
            for (int k = 0; k < KK2; k++) {
                float a = m[k] * inv;
                float ph = (float)h + (float)(k / 3 - 1) + om[g * 18 + 2 * k]     * 0.1f;
                float pw = (float)w + (float)(k % 3 - 1) + om[g * 18 + 2 * k + 1] * 0.1f;
                ph = fminf(fmaxf(ph, 0.f), (float)(Hh - 1));
                pw = fminf(fmaxf(pw, 0.f), (float)(Wd - 1));
                int hf = (int)ph;
                int wf = (int)pw;
                float fh = ph - (float)hf;
                float fw = pw - (float)wf;
                int hl = min(max(hf - (h0 - 2), 0), 11);
                int wl = min(max(wf - (w0 - 2), 0), 11);
                float4 wv;
                wv.x = a * (1.f - fh) * (1.f - fw);
                wv.y = a * (1.f - fh) * fw;
                wv.z = a * fh * (1.f - fw);
                wv.w = a * fh * fw;
                tapw[tid * KK2 + k] = wv;
                tapi[tid * KK2 + k] = (hl * 13 + wl) * 16;
            }
        } else {
            // --- stage 13x13x32 fp16 window of group g (threads 64..255) ---
            for (int idx = tid - 64; idx < 13 * 13 * 8; idx += 192) {
                int cell = idx >> 3;
                int c4 = idx & 7;
                int hi = cell / 13, wi = cell % 13;
                int row = min(max(h0 - 2 + hi, 0), Hh - 1);
                int col = min(max(w0 - 2 + wi, 0), Wd - 1);
                uint2 v = *reinterpret_cast<const uint2*>(
                    &xproj[(((size_t)(b * Hh + row)) * Wd + col) * Cc + g * GC + c4 * 4]);
                xs[cell * 16 + c4 * 2]     = *reinterpret_cast<__half2*>(&v.x);
                xs[cell * 16 + c4 * 2 + 1] = *reinterpret_cast<__half2*>(&v.y);
            }
        }
        __syncthreads();

        // --- sample + write fragment-major bf16 hi/lo into As ---
        const int ktile = g * 2 + (ch >> 3);
        const int tigw = ch & 3;
        const int khalf = (ch >> 2) & 1;
#pragma unroll
        for (int pass = 0; pass < 4; pass++) {
            int p = wid * 8 + pass * 2 + half;
            float2 acc = make_float2(0.f, 0.f);
#pragma unroll
            for (int k = 0; k < KK2; k++) {
                float4 wv = tapw[p * KK2 + k];
                int c00 = tapi[p * KK2 + k] + ch;
                float2 v00 = __half22float2(xs[c00]);
                float2 v01 = __half22float2(xs[c00 + 16]);
                float2 v10 = __half22float2(xs[c00 + 208]);
                float2 v11 = __half22float2(xs[c00 + 224]);
                acc.x = fmaf(wv.x, v00.x, acc.x);
                acc.x = fmaf(wv.y, v01.x, acc.x);
                acc.x = fmaf(wv.z, v10.x, acc.x);
                acc.x = fmaf(wv.w, v11.x, acc.x);
                acc.y = fmaf(wv.x, v00.y, acc.y);
                acc.y = fmaf(wv.y, v01.y, acc.y);
                acc.y = fmaf(wv.z, v10.y, acc.y);
                acc.y = fmaf(wv.w, v11.y, acc.y);
            }
            int mb = p >> 4;
            int gp = p & 7;
            int half_r = (p >> 3) & 1;
            int reg = half_r + 2 * khalf;
            unsigned hi = bf16pair(acc.x, acc.y);
            __nv_bfloat162 h2 = *reinterpret_cast<__nv_bfloat162*>(&hi);
            unsigned lo = bf16pair(acc.x - __bfloat162float(h2.x),
                                   acc.y - __bfloat162float(h2.y));
            As[((0 * 12 + ktile) * 4 + mb) * 128 + (gp * 4 + tigw) * 4 + reg] = hi;
            As[((1 * 12 + ktile) * 4 + mb) * 128 + (gp * 4 + tigw) * 4 + reg] = lo;
        }
    }
    __syncthreads();

    // ================= GEMM phase: [64,192] @ [192,192] bf16x3 =================
    const uint2* wf2 = reinterpret_cast<const uint2*>(wfrag);
    float acc[4][3][4];
#pragma unroll
    for (int mt = 0; mt < 4; mt++)
#pragma unroll
        for (int nt = 0; nt < 3; nt++)
#pragma unroll
            for (int r = 0; r < 4; r++) acc[mt][nt][r] = 0.f;

    uint2 bh[2][3], bl[2][3];
    auto loadB = [&](int kt, int pb) {
#pragma unroll
        for (int nt = 0; nt < 3; nt++) {
            int n8 = wid * 3 + nt;
            bh[pb][nt] = wf2[((kt * 2 + 0) * 24 + n8) * 32 + lane];
            bl[pb][nt] = wf2[((kt * 2 + 1) * 24 + n8) * 32 + lane];
        }
    };
    loadB(0, 0);
    int pb = 0;
#pragma unroll
    for (int kt = 0; kt < 12; kt++) {
        if (kt < 11) loadB(kt + 1, pb ^ 1);
        unsigned ah[4][4], al[4][4];
#pragma unroll
        for (int mb = 0; mb < 4; mb++) {
            uint4 u = *reinterpret_cast<const uint4*>(
                &As[((0 * 12 + kt) * 4 + mb) * 128 + lane * 4]);
            ah[mb][0] = u.x; ah[mb][1] = u.y; ah[mb][2] = u.z; ah[mb][3] = u.w;
            uint4 v = *reinterpret_cast<const uint4*>(
                &As[((1 * 12 + kt) * 4 + mb) * 128 + lane * 4]);
            al[mb][0] = v.x; al[mb][1] = v.y; al[mb][2] = v.z; al[mb][3] = v.w;
        }
#pragma unroll
        for (int mt = 0; mt < 4; mt++)
#pragma unroll
            for (int nt = 0; nt < 3; nt++) {
                mma_bf16(acc[mt][nt], ah[mt], bh[pb][nt].x, bh[pb][nt].y);
                mma_bf16(acc[mt][nt], ah[mt], bl[pb][nt].x, bl[pb][nt].y);
                mma_bf16(acc[mt][nt], al[mt], bh[pb][nt].x, bh[pb][nt].y);
            }
        pb ^= 1;
    }

    const int gid = lane >> 2;
    const int tig = lane & 3;
#pragma unroll
    for (int mt = 0; mt < 4; mt++) {
#pragma unroll
        for (int rr = 0; rr < 2; rr++) {
            int p = mt * 16 + rr * 8 + gid;
            size_t pix = ((size_t)(b * Hh + h0 + (p >> 3)) * Wd + w0 + (p & 7));
#pragma unroll
            for (int nt = 0; nt < 3; nt++) {
                int n = (wid * 3 + nt) * 8 + tig * 2;
                float2 v;
                v.x = acc[mt][nt][rr * 2 + 0] + bias[n];
                v.y = acc[mt][nt][rr * 2 + 1] + bias[n + 1];
                *reinterpret_cast<float2*>(&out[pix * Cc + n]) = v;
            }
        }
    }
}

// ---------------------------------------------------------------------------
// Launch
// ---------------------------------------------------------------------------
extern "C" void kernel_launch(void* const* d_in, const int* in_sizes, int n_in,
                              void* d_out, int out_size)
{
    const float* x      = (const float*)d_in[0];
    const float* w_in   = (const float*)d_in[1];
    const float* b_in   = (const float*)d_in[2];
    const float* w_dw   = (const float*)d_in[3];
    const float* b_dw   = (const float*)d_in[4];
    const float* w_pw   = (const float*)d_in[5];
    const float* b_pw   = (const float*)d_in[6];
    const float* w_off  = (const float*)d_in[7];
    const float* b_off  = (const float*)d_in[8];
    const float* w_mask = (const float*)d_in[9];
    const float* b_mask = (const float*)d_in[10];
    const float* w_out  = (const float*)d_in[11];
    const float* b_out  = (const float*)d_in[12];
    float* out = (float*)d_out;

    __half* xproj;
    float *tmp, *offmsk, *wf, *bfu;
    unsigned *wfin, *wfout, *wff;
    cudaGetSymbolAddress((void**)&xproj,  g_xproj);
    cudaGetSymbolAddress((void**)&tmp,    g_tmp);
    cudaGetSymbolAddress((void**)&offmsk, g_offmsk);
    cudaGetSymbolAddress((void**)&wf,     g_wf);
    cudaGetSymbolAddress((void**)&bfu,    g_bfuse);
    cudaGetSymbolAddress((void**)&wfin,   g_wfrag_in);
    cudaGetSymbolAddress((void**)&wfout,  g_wfrag_out);
    cudaGetSymbolAddress((void**)&wff,    g_wffrag);

    cudaFuncSetAttribute(deform_gemm, cudaFuncAttributeMaxDynamicSharedMemorySize, SM_TOTAL);

    // 0. weight prep: fuse pw into offset/mask (fp32), then pack all fragments
    fuse_wb<<<Cc + 1, 192>>>(w_pw, b_pw, w_off, w_mask, b_off, b_mask, wf, bfu);
    prep_all<<<(26496 + 255) / 256, 256>>>(w_in, w_out, wf, wfin, wfout, wff);
    // 1. x_proj = x @ w_in + b_in  (bf16x3, smem-free, fp16 out, full-N blocks)
    gemm_x3_fp16out<<<M_PIX / 128, 256>>>(x, wfin, b_in, xproj);
    // 2. depthwise 3x3 + SiLU -> bf16 tmp
    {
        size_t n = (size_t)(M_PIX / 4) * (Cc / 4);
        dw_silu<<<(unsigned)((n + 255) / 256), 256>>>(
            (const float4*)x, (const float4*)w_dw, (const float4*)b_dw,
            (__nv_bfloat16*)tmp);
    }
    // 3. [offsets|mask] = dwout_bf16 @ W_f + b_f  (plain bf16, smem-free)
    gemm_plain_direct<<<dim3(3, M_PIX / 256), 256>>>(
        (const __nv_bfloat16*)tmp, wff, bfu, offmsk);
    // 4+5. fused softmax + deformable sampling (fp16 window) + final GEMM -> out
    deform_gemm<<<2048, 256, SM_TOTAL>>>(xproj, offmsk, wfout, b_out, out);
}

// round 9
// speedup vs baseline: 1.5545x; 1.1988x over previous
#include <cuda_runtime.h>
#include <cuda_bf16.h>
#include <cuda_fp16.h>
#include <math.h>

#define Bn   8
#define Hh   128
#define Wd   128
#define Cc   192
#define Gg   6
#define GC   32
#define KK2  9
#define NFUS 162     // 108 offsets + 54 mask logits
#define M_PIX (Bn*Hh*Wd)   // 131072

// Scratch (device globals — no runtime allocation allowed)
__device__ __half g_xproj [(size_t)M_PIX * Cc];      // x_proj as fp16
__device__ float g_tmp   [(size_t)M_PIX * Cc / 2];   // dw output as bf16
__device__ float g_offmsk[(size_t)M_PIX * NFUS];
__device__ float g_wf    [Cc * NFUS];
__device__ float g_bfuse [NFUS];
__device__ unsigned g_wfrag_in [12 * 24 * 64];       // w_in  fragment-major fp16
__device__ unsigned g_wfrag_out[12 * 24 * 64];       // w_out fragment-major fp16
__device__ unsigned g_wffrag   [12 * 21 * 64];       // fused W fragment-major bf16, N padded->168

// ---------------------------------------------------------------------------
// helpers
// ---------------------------------------------------------------------------
__device__ __forceinline__ unsigned bf16pair(float a, float b) {
    __nv_bfloat162 t = __floats2bfloat162_rn(a, b);
    return *reinterpret_cast<unsigned*>(&t);
}
__device__ __forceinline__ unsigned f16pair(float a, float b) {
    __half2 t = __floats2half2_rn(a, b);   // a -> low half (even k)
    return *reinterpret_cast<unsigned*>(&t);
}
__device__ __forceinline__ void mma_bf16(float* d, const unsigned* a, unsigned b0, unsigned b1) {
    asm volatile(
        "mma.sync.aligned.m16n8k16.row.col.f32.bf16.bf16.f32 "
        "{%0,%1,%2,%3}, {%4,%5,%6,%7}, {%8,%9}, {%0,%1,%2,%3};\n"
        : "+f"(d[0]), "+f"(d[1]), "+f"(d[2]), "+f"(d[3])
        : "r"(a[0]), "r"(a[1]), "r"(a[2]), "r"(a[3]), "r"(b0), "r"(b1));
}
__device__ __forceinline__ void mma_f16(float* d, const unsigned* a, unsigned b0, unsigned b1) {
    asm volatile(
        "mma.sync.aligned.m16n8k16.row.col.f32.f16.f16.f32 "
        "{%0,%1,%2,%3}, {%4,%5,%6,%7}, {%8,%9}, {%0,%1,%2,%3};\n"
        : "+f"(d[0]), "+f"(d[1]), "+f"(d[2]), "+f"(d[3])
        : "r"(a[0]), "r"(a[1]), "r"(a[2]), "r"(a[3]), "r"(b0), "r"(b1));
}

// ---------------------------------------------------------------------------
// Weight packing (one kernel for all three packs)
// fp16 pack layout: wfrag[(kt*24 + n8)*64 + lane*2 + which]
// wf (bf16) pack layout (N padded to 168): wffrag[(kt*21 + n8)*64 + lane*2 + which]
// ---------------------------------------------------------------------------
__device__ __forceinline__ void pack192h(const float* __restrict__ w,
                                         unsigned* __restrict__ wfrag, int i)
{
    int kt = i / (24 * 32);
    int r = i % (24 * 32);
    int n8 = r / 32;
    int lane = r % 32;
    int gid = lane >> 2, tig = lane & 3;
    int n = n8 * 8 + gid;
#pragma unroll
    for (int which = 0; which < 2; which++) {
        int k0 = kt * 16 + which * 8 + tig * 2;
        float v0 = w[(size_t)k0 * Cc + n];
        float v1 = w[(size_t)(k0 + 1) * Cc + n];
        wfrag[(kt * 24 + n8) * 64 + lane * 2 + which] = f16pair(v0, v1);
    }
}

__device__ __forceinline__ void packwf(const float* __restrict__ wf,
                                       unsigned* __restrict__ wffrag, int i)
{
    int kt = i / (21 * 32);
    int r = i % (21 * 32);
    int n8 = r / 32;
    int lane = r % 32;
    int gid = lane >> 2, tig = lane & 3;
    int n = n8 * 8 + gid;
#pragma unroll
    for (int which = 0; which < 2; which++) {
        int k0 = kt * 16 + which * 8 + tig * 2;
        float v0 = (n < NFUS) ? wf[(size_t)k0 * NFUS + n] : 0.f;
        float v1 = (n < NFUS) ? wf[(size_t)(k0 + 1) * NFUS + n] : 0.f;
        wffrag[(kt * 21 + n8) * 64 + lane * 2 + which] = bf16pair(v0, v1);
    }
}

__global__ void prep_all(const float* __restrict__ w_in, const float* __restrict__ w_out,
                         const float* __restrict__ wf,
                         unsigned* __restrict__ fin, unsigned* __restrict__ fout,
                         unsigned* __restrict__ ffw)
{
    int i = blockIdx.x * blockDim.x + threadIdx.x;
    if (i < 9216)              pack192h(w_in,  fin,  i);
    else if (i < 18432)        pack192h(w_out, fout, i - 9216);
    else if (i < 18432 + 8064) packwf(wf, ffw, i - 18432);
}

// ---------------------------------------------------------------------------
// Weight fusion (exact fp32): W_f = w_pw @ [w_off | w_mask]; last block: bias.
// ---------------------------------------------------------------------------
__global__ void fuse_wb(const float* __restrict__ wpw, const float* __restrict__ bpw,
                        const float* __restrict__ woff, const float* __restrict__ wmask,
                        const float* __restrict__ boff, const float* __restrict__ bmask,
                        float* __restrict__ wf, float* __restrict__ bf)
{
    int n = threadIdx.x;
    if (n >= NFUS) return;
    int blk = blockIdx.x;
    if (blk < Cc) {
        const float* wrow = wpw + (size_t)blk * Cc;
        float acc = 0.f;
        if (n < 108) {
            for (int o = 0; o < Cc; o++) acc = fmaf(wrow[o], woff[(size_t)o * 108 + n], acc);
        } else {
            int n2 = n - 108;
            for (int o = 0; o < Cc; o++) acc = fmaf(wrow[o], wmask[(size_t)o * 54 + n2], acc);
        }
        wf[(size_t)blk * NFUS + n] = acc;
    } else {
        float acc = (n < 108) ? boff[n] : bmask[n - 108];
        if (n < 108) {
            for (int o = 0; o < Cc; o++) acc = fmaf(bpw[o], woff[(size_t)o * 108 + n], acc);
        } else {
            int n2 = n - 108;
            for (int o = 0; o < Cc; o++) acc = fmaf(bpw[o], wmask[(size_t)o * 54 + n2], acc);
        }
        bf[n] = acc;
    }
}

// ---------------------------------------------------------------------------
// Smem-free fp16 GEMM, full N=192 per block, fp16 output.
// Grid M/128, block 256 (8 warps: 4 along M x 2 along N). Warp tile 32x96.
// ---------------------------------------------------------------------------
__global__ __launch_bounds__(256) void gemm_f16(
    const float* __restrict__ A, const unsigned* __restrict__ wfrag,
    const float* __restrict__ bias, __half* __restrict__ C)
{
    const int tid = threadIdx.x;
    const int wid = tid >> 5;
    const int lane = tid & 31;
    const int gid = lane >> 2;
    const int tig = lane & 3;
    const int bm = blockIdx.x * 128 + (wid & 3) * 32;
    const int n8base = (wid >> 2) * 12;          // 2 n-halves of 96 cols
    const uint2* wf2 = reinterpret_cast<const uint2*>(wfrag);

    float acc[2][12][4];
#pragma unroll
    for (int mt = 0; mt < 2; mt++)
#pragma unroll
        for (int nt = 0; nt < 12; nt++)
#pragma unroll
            for (int r = 0; r < 4; r++) acc[mt][nt][r] = 0.f;

    const float* ap0[2];
    const float* ap1[2];
#pragma unroll
    for (int mt = 0; mt < 2; mt++) {
        ap0[mt] = A + (size_t)(bm + mt * 16 + gid) * Cc + tig * 2;
        ap1[mt] = A + (size_t)(bm + mt * 16 + gid + 8) * Cc + tig * 2;
    }

    float2 av[2][4];
    auto loadA = [&](int kt) {
#pragma unroll
        for (int mt = 0; mt < 2; mt++) {
            av[mt][0] = *reinterpret_cast<const float2*>(ap0[mt] + kt * 16);
            av[mt][1] = *reinterpret_cast<const float2*>(ap1[mt] + kt * 16);
            av[mt][2] = *reinterpret_cast<const float2*>(ap0[mt] + kt * 16 + 8);
            av[mt][3] = *reinterpret_cast<const float2*>(ap1[mt] + kt * 16 + 8);
        }
    };

    loadA(0);
#pragma unroll
    for (int kt = 0; kt < 12; kt++) {
        unsigned ah[2][4];
#pragma unroll
        for (int mt = 0; mt < 2; mt++)
#pragma unroll
            for (int r = 0; r < 4; r++)
                ah[mt][r] = f16pair(av[mt][r].x, av[mt][r].y);
        if (kt < 11) loadA(kt + 1);

#pragma unroll
        for (int nt = 0; nt < 12; nt++) {
            uint2 bh = wf2[(size_t)(kt * 24 + n8base + nt) * 32 + lane];
#pragma unroll
            for (int mt = 0; mt < 2; mt++)
                mma_f16(acc[mt][nt], ah[mt], bh.x, bh.y);
        }
    }

#pragma unroll
    for (int mt = 0; mt < 2; mt++) {
        int row0 = bm + mt * 16 + gid;
#pragma unroll
        for (int nt = 0; nt < 12; nt++) {
            int col = (n8base + nt) * 8 + tig * 2;
            float2 bv = *reinterpret_cast<const float2*>(&bias[col]);
            __half2 h0 = __floats2half2_rn(acc[mt][nt][0] + bv.x, acc[mt][nt][1] + bv.y);
            __half2 h1 = __floats2half2_rn(acc[mt][nt][2] + bv.x, acc[mt][nt][3] + bv.y);
            *reinterpret_cast<__half2*>(&C[(size_t)row0 * Cc + col]) = h0;
            *reinterpret_cast<__half2*>(&C[(size_t)(row0 + 8) * Cc + col]) = h1;
        }
    }
}

// ---------------------------------------------------------------------------
// Smem-free plain bf16 GEMM: C[M,162] = A(bf16)[M,192] @ WFfrag + bias.
// ---------------------------------------------------------------------------
__global__ __launch_bounds__(256) void gemm_plain_direct(
    const __nv_bfloat16* __restrict__ A, const unsigned* __restrict__ wffrag,
    const float* __restrict__ bias, float* __restrict__ C)
{
    const int tid = threadIdx.x;
    const int wid = tid >> 5;
    const int lane = tid & 31;
    const int gid = lane >> 2;
    const int tig = lane & 3;
    const int bn8 = blockIdx.x * 7;
    const int bm = blockIdx.y * 256 + wid * 32;
    const uint2* wf2 = reinterpret_cast<const uint2*>(wffrag);

    float acc[2][7][4];
#pragma unroll
    for (int mt = 0; mt < 2; mt++)
#pragma unroll
        for (int nt = 0; nt < 7; nt++)
#pragma unroll
            for (int r = 0; r < 4; r++) acc[mt][nt][r] = 0.f;

    const __nv_bfloat16* ap0[2];
    const __nv_bfloat16* ap1[2];
#pragma unroll
    for (int mt = 0; mt < 2; mt++) {
        ap0[mt] = A + (size_t)(bm + mt * 16 + gid) * Cc + tig * 2;
        ap1[mt] = A + (size_t)(bm + mt * 16 + gid + 8) * Cc + tig * 2;
    }

    unsigned ar[2][4];
    auto loadA = [&](int kt) {
#pragma unroll
        for (int mt = 0; mt < 2; mt++) {
            ar[mt][0] = *reinterpret_cast<const unsigned*>(ap0[mt] + kt * 16);
            ar[mt][1] = *reinterpret_cast<const unsigned*>(ap1[mt] + kt * 16);
            ar[mt][2] = *reinterpret_cast<const unsigned*>(ap0[mt] + kt * 16 + 8);
            ar[mt][3] = *reinterpret_cast<const unsigned*>(ap1[mt] + kt * 16 + 8);
        }
    };

    loadA(0);
#pragma unroll
    for (int kt = 0; kt < 12; kt++) {
        unsigned a0[2][4];
#pragma unroll
        for (int mt = 0; mt < 2; mt++)
#pragma unroll
            for (int r = 0; r < 4; r++) a0[mt][r] = ar[mt][r];
        if (kt < 11) loadA(kt + 1);

#pragma unroll
        for (int nt = 0; nt < 7; nt++) {
            uint2 bh = wf2[(size_t)(kt * 21 + bn8 + nt) * 32 + lane];
#pragma unroll
            for (int mt = 0; mt < 2; mt++)
                mma_bf16(acc[mt][nt], a0[mt], bh.x, bh.y);
        }
    }

#pragma unroll
    for (int mt = 0; mt < 2; mt++) {
        int row0 = bm + mt * 16 + gid;
#pragma unroll
        for (int nt = 0; nt < 7; nt++) {
            int col = (bn8 + nt) * 8 + tig * 2;
            if (col < NFUS) {
                float b0 = bias[col];
                C[(size_t)row0 * NFUS + col]       = acc[mt][nt][0] + b0;
                C[(size_t)(row0 + 8) * NFUS + col] = acc[mt][nt][2] + b0;
            }
            if (col + 1 < NFUS) {
                float b1 = bias[col + 1];
                C[(size_t)row0 * NFUS + col + 1]       = acc[mt][nt][1] + b1;
                C[(size_t)(row0 + 8) * NFUS + col + 1] = acc[mt][nt][3] + b1;
            }
        }
    }
}

// ---------------------------------------------------------------------------
// Depthwise 3x3 + bias + SiLU, register-blocked, bf16 output.
// ---------------------------------------------------------------------------
__global__ __launch_bounds__(256) void dw_silu(
    const float4* __restrict__ x, const float4* __restrict__ wdw,
    const float4* __restrict__ bdw, __nv_bfloat16* __restrict__ out)
{
    const int C4 = Cc / 4;        // 48
    const int RW = Wd / 4;
    const size_t total = (size_t)(M_PIX / 4) * C4;
    size_t idx = (size_t)blockIdx.x * blockDim.x + threadIdx.x;
    if (idx >= total) return;

    int c4 = (int)(idx % C4);
    int run = (int)(idx / C4);
    int w0 = (run % RW) * 4;
    int h = (run / RW) % Hh;
    int b = run / (RW * Hh);

    float4 bias = bdw[c4];
    float4 acc[4] = {bias, bias, bias, bias};
    const float4 z = make_float4(0.f, 0.f, 0.f, 0.f);

#pragma unroll
    for (int ky = 0; ky < 3; ky++) {
        int hy = h + ky - 1;
        if (hy < 0 || hy >= Hh) continue;
        const float4* row = x + ((size_t)(b * Hh + hy) * Wd) * C4 + c4;
        float4 xv[6];
        xv[0] = (w0 > 0) ? row[(size_t)(w0 - 1) * C4] : z;
#pragma unroll
        for (int t = 0; t < 4; t++) xv[1 + t] = row[(size_t)(w0 + t) * C4];
        xv[5] = (w0 + 4 < Wd) ? row[(size_t)(w0 + 4) * C4] : z;

        float4 wt[3];
#pragma unroll
        for (int kx = 0; kx < 3; kx++) wt[kx] = wdw[(ky * 3 + kx) * C4 + c4];

#pragma unroll
        for (int ow = 0; ow < 4; ow++) {
#pragma unroll
            for (int kx = 0; kx < 3; kx++) {
                float4 v = xv[ow + kx];
                acc[ow].x = fmaf(v.x, wt[kx].x, acc[ow].x);
                acc[ow].y = fmaf(v.y, wt[kx].y, acc[ow].y);
                acc[ow].z = fmaf(v.z, wt[kx].z, acc[ow].z);
                acc[ow].w = fmaf(v.w, wt[kx].w, acc[ow].w);
            }
        }
    }

#pragma unroll
    for (int ow = 0; ow < 4; ow++) {
        float4 a = acc[ow];
        a.x = a.x / (1.f + __expf(-a.x));
        a.y = a.y / (1.f + __expf(-a.y));
        a.z = a.z / (1.f + __expf(-a.z));
        a.w = a.w / (1.f + __expf(-a.w));
        uint2 pk;
        pk.x = bf16pair(a.x, a.y);
        pk.y = bf16pair(a.z, a.w);
        *reinterpret_cast<uint2*>(
            &out[((size_t)(b * Hh + h) * Wd + (w0 + ow)) * Cc + c4 * 4]) = pk;
    }
}

// ---------------------------------------------------------------------------
// FUSED: softmax + deformable bilinear sampling (fp16) + final GEMM (fp16).
// smem: xs 10816 + tapw 9216 + tapi 2304 + As 24576 = 46912 B (4 blocks/SM).
// ---------------------------------------------------------------------------
#define SM_XS    0
#define SM_TW    10816
#define SM_TI    20032
#define SM_AS    22336
#define SM_TOTAL 46912

__global__ __launch_bounds__(256) void deform_gemm(
    const __half* __restrict__ xproj, const float* __restrict__ offmsk,
    const unsigned* __restrict__ wfrag, const float* __restrict__ bias,
    float* __restrict__ out)
{
    extern __shared__ char smem_raw[];
    __half2* xs = reinterpret_cast<__half2*>(smem_raw + SM_XS);        // [169][16]
    float4* tapw = reinterpret_cast<float4*>(smem_raw + SM_TW);        // [64][9]
    int* tapi = reinterpret_cast<int*>(smem_raw + SM_TI);              // [64][9]
    unsigned* As = reinterpret_cast<unsigned*>(smem_raw + SM_AS);      // [12][4][32][4] fp16

    const int tile = blockIdx.x;
    const int tid = threadIdx.x;
    const int wid = tid >> 5;
    const int lane = tid & 31;

    const int b  = tile >> 8;
    const int ty = (tile >> 4) & 15;
    const int tx = tile & 15;
    const int h0 = ty * 8, w0 = tx * 8;

    const int half = lane >> 4;
    const int ch = lane & 15;

    for (int g = 0; g < Gg; g++) {
        if (g) __syncthreads();   // previous group done reading xs/meta

        if (tid < 64) {
            // --- meta: softmax + folded bilinear weights for pixel tid ---
            int py = tid >> 3, px = tid & 7;
            int h = h0 + py, w = w0 + px;
            const float* om = offmsk + (((size_t)(b * Hh + h)) * Wd + w) * NFUS;
            float m[KK2], mx = -1e30f;
#pragma unroll
            for (int k = 0; k < KK2; k++) { m[k] = om[108 + g * KK2 + k]; mx = fmaxf(mx, m[k]); }
            float sum = 0.f;
#pragma unroll
            for (int k = 0; k < KK2; k++) { m[k] = __expf(m[k] - mx); sum += m[k]; }
            float inv = 1.f / sum;
#pragma unroll
            for (int k = 0; k < KK2; k++) {
                float a = m[k] * inv;
                float ph = (float)h + (float)(k / 3 - 1) + om[g * 18 + 2 * k]     * 0.1f;
                float pw = (float)w + (float)(k % 3 - 1) + om[g * 18 + 2 * k + 1] * 0.1f;
                ph = fminf(fmaxf(ph, 0.f), (float)(Hh - 1));
                pw = fminf(fmaxf(pw, 0.f), (float)(Wd - 1));
                int hf = (int)ph;
                int wf = (int)pw;
                float fh = ph - (float)hf;
                float fw = pw - (float)wf;
                int hl = min(max(hf - (h0 - 2), 0), 11);
                int wl = min(max(wf - (w0 - 2), 0), 11);
                float4 wv;
                wv.x = a * (1.f - fh) * (1.f - fw);
                wv.y = a * (1.f - fh) * fw;
                wv.z = a * fh * (1.f - fw);
                wv.w = a * fh * fw;
                tapw[tid * KK2 + k] = wv;
                tapi[tid * KK2 + k] = (hl * 13 + wl) * 16;
            }
        } else {
            // --- stage 13x13x32 fp16 window of group g (threads 64..255) ---
            for (int idx = tid - 64; idx < 13 * 13 * 8; idx += 192) {
                int cell = idx >> 3;
                int c4 = idx & 7;
                int hi = cell / 13, wi = cell % 13;
                int row = min(max(h0 - 2 + hi, 0), Hh - 1);
                int col = min(max(w0 - 2 + wi, 0), Wd - 1);
                uint2 v = *reinterpret_cast<const uint2*>(
                    &xproj[(((size_t)(b * Hh + row)) * Wd + col) * Cc + g * GC + c4 * 4]);
                xs[cell * 16 + c4 * 2]     = *reinterpret_cast<__half2*>(&v.x);
                xs[cell * 16 + c4 * 2 + 1] = *reinterpret_cast<__half2*>(&v.y);
            }
        }
        __syncthreads();

        // --- sample + write fragment-major fp16 into As ---
        const int ktile = g * 2 + (ch >> 3);
        const int tigw = ch & 3;
        const int khalf = (ch >> 2) & 1;
#pragma unroll
        for (int pass = 0; pass < 4; pass++) {
            int p = wid * 8 + pass * 2 + half;
            float2 acc = make_float2(0.f, 0.f);
#pragma unroll
            for (int k = 0; k < KK2; k++) {
                float4 wv = tapw[p * KK2 + k];
                int c00 = tapi[p * KK2 + k] + ch;
                float2 v00 = __half22float2(xs[c00]);
                float2 v01 = __half22float2(xs[c00 + 16]);
                float2 v10 = __half22float2(xs[c00 + 208]);
                float2 v11 = __half22float2(xs[c00 + 224]);
                acc.x = fmaf(wv.x, v00.x, acc.x);
                acc.x = fmaf(wv.y, v01.x, acc.x);
                acc.x = fmaf(wv.z, v10.x, acc.x);
                acc.x = fmaf(wv.w, v11.x, acc.x);
                acc.y = fmaf(wv.x, v00.y, acc.y);
                acc.y = fmaf(wv.y, v01.y, acc.y);
                acc.y = fmaf(wv.z, v10.y, acc.y);
                acc.y = fmaf(wv.w, v11.y, acc.y);
            }
            int mb = p >> 4;
            int gp = p & 7;
            int half_r = (p >> 3) & 1;
            int reg = half_r + 2 * khalf;
            As[(ktile * 4 + mb) * 128 + (gp * 4 + tigw) * 4 + reg] = f16pair(acc.x, acc.y);
        }
    }
    __syncthreads();

    // ================= GEMM phase: [64,192] @ [192,192] fp16 =================
    const uint2* wf2 = reinterpret_cast<const uint2*>(wfrag);
    float acc[4][3][4];
#pragma unroll
    for (int mt = 0; mt < 4; mt++)
#pragma unroll
        for (int nt = 0; nt < 3; nt++)
#pragma unroll
            for (int r = 0; r < 4; r++) acc[mt][nt][r] = 0.f;

    uint2 bh[2][3];
    auto loadB = [&](int kt, int pb) {
#pragma unroll
        for (int nt = 0; nt < 3; nt++)
            bh[pb][nt] = wf2[(kt * 24 + wid * 3 + nt) * 32 + lane];
    };
    loadB(0, 0);
    int pb = 0;
#pragma unroll
    for (int kt = 0; kt < 12; kt++) {
        if (kt < 11) loadB(kt + 1, pb ^ 1);
        unsigned ah[4][4];
#pragma unroll
        for (int mb = 0; mb < 4; mb++) {
            uint4 u = *reinterpret_cast<const uint4*>(&As[(kt * 4 + mb) * 128 + lane * 4]);
            ah[mb][0] = u.x; ah[mb][1] = u.y; ah[mb][2] = u.z; ah[mb][3] = u.w;
        }
#pragma unroll
        for (int mt = 0; mt < 4; mt++)
#pragma unroll
            for (int nt = 0; nt < 3; nt++)
                mma_f16(acc[mt][nt], ah[mt], bh[pb][nt].x, bh[pb][nt].y);
        pb ^= 1;
    }

    const int gid = lane >> 2;
    const int tig = lane & 3;
#pragma unroll
    for (int mt = 0; mt < 4; mt++) {
#pragma unroll
        for (int rr = 0; rr < 2; rr++) {
            int p = mt * 16 + rr * 8 + gid;
            size_t pix = ((size_t)(b * Hh + h0 + (p >> 3)) * Wd + w0 + (p & 7));
#pragma unroll
            for (int nt = 0; nt < 3; nt++) {
                int n = (wid * 3 + nt) * 8 + tig * 2;
                float2 v;
                v.x = acc[mt][nt][rr * 2 + 0] + bias[n];
                v.y = acc[mt][nt][rr * 2 + 1] + bias[n + 1];
                *reinterpret_cast<float2*>(&out[pix * Cc + n]) = v;
            }
        }
    }
}

// ---------------------------------------------------------------------------
// Launch
// ---------------------------------------------------------------------------
extern "C" void kernel_launch(void* const* d_in, const int* in_sizes, int n_in,
                              void* d_out, int out_size)
{
    const float* x      = (const float*)d_in[0];
    const float* w_in   = (const float*)d_in[1];
    const float* b_in   = (const float*)d_in[2];
    const float* w_dw   = (const float*)d_in[3];
    const float* b_dw   = (const float*)d_in[4];
    const float* w_pw   = (const float*)d_in[5];
    const float* b_pw   = (const float*)d_in[6];
    const float* w_off  = (const float*)d_in[7];
    const float* b_off  = (const float*)d_in[8];
    const float* w_mask = (const float*)d_in[9];
    const float* b_mask = (const float*)d_in[10];
    const float* w_out  = (const float*)d_in[11];
    const float* b_out  = (const float*)d_in[12];
    float* out = (float*)d_out;

    __half* xproj;
    float *tmp, *offmsk, *wf, *bfu;
    unsigned *wfin, *wfout, *wff;
    cudaGetSymbolAddress((void**)&xproj,  g_xproj);
    cudaGetSymbolAddress((void**)&tmp,    g_tmp);
    cudaGetSymbolAddress((void**)&offmsk, g_offmsk);
    cudaGetSymbolAddress((void**)&wf,     g_wf);
    cudaGetSymbolAddress((void**)&bfu,    g_bfuse);
    cudaGetSymbolAddress((void**)&wfin,   g_wfrag_in);
    cudaGetSymbolAddress((void**)&wfout,  g_wfrag_out);
    cudaGetSymbolAddress((void**)&wff,    g_wffrag);

    cudaFuncSetAttribute(deform_gemm, cudaFuncAttributeMaxDynamicSharedMemorySize, SM_TOTAL);

    // 0. weight prep: fuse pw into offset/mask (fp32), then pack all fragments
    fuse_wb<<<Cc + 1, 192>>>(w_pw, b_pw, w_off, w_mask, b_off, b_mask, wf, bfu);
    prep_all<<<(26496 + 255) / 256, 256>>>(w_in, w_out, wf, wfin, wfout, wff);
    // 1. x_proj = x @ w_in + b_in  (fp16 mma, smem-free, fp16 out)
    gemm_f16<<<M_PIX / 128, 256>>>(x, wfin, b_in, xproj);
    // 2. depthwise 3x3 + SiLU -> bf16 tmp
    {
        size_t n = (size_t)(M_PIX / 4) * (Cc / 4);
        dw_silu<<<(unsigned)((n + 255) / 256), 256>>>(
            (const float4*)x, (const float4*)w_dw, (const float4*)b_dw,
            (__nv_bfloat16*)tmp);
    }
    // 3. [offsets|mask] = dwout_bf16 @ W_f + b_f  (plain bf16, smem-free)
    gemm_plain_direct<<<dim3(3, M_PIX / 256), 256>>>(
        (const __nv_bfloat16*)tmp, wff, bfu, offmsk);
    // 4+5. fused softmax + deformable sampling + final GEMM (fp16) -> out
    deform_gemm<<<2048, 256, SM_TOTAL>>>(xproj, offmsk, wfout, b_out, out);
}